// round 1
// baseline (speedup 1.0000x reference)
#include <cuda_runtime.h>
#include <cuda_bf16.h>

// Problem constants (fixed by dataset)
#define BATCH 4
#define SEQ   4096
#define DIM   512
#define DK    64
#define BAND  128
#define SCALE 0.125f            // 1/sqrt(64)
#define ROWS  (BATCH*SEQ)       // 16384
#define MTOT  (2*ROWS)          // 32768 (q rows then kv rows)

// Scratch (device globals; no allocation allowed)
__device__ float g_q[ROWS * DK];
__device__ float g_kv[ROWS * DK];
__device__ float g_att[ROWS * DK];

// ---------------------------------------------------------------------------
// Kernel 1: shared input projection.  dst = src @ Wi + bi
// One GEMM over 32768 rows (query rows then value rows), N=64, K=512.
// Block: 64 rows x 64 cols, 256 threads, 4x4 micro-tile.
// ---------------------------------------------------------------------------
__global__ void __launch_bounds__(256) proj_kernel(const float* __restrict__ query,
                                                   const float* __restrict__ value,
                                                   const float* __restrict__ Wi,
                                                   const float* __restrict__ bi)
{
    __shared__ float At[64][68];   // A chunk transposed: [k][row]
    __shared__ float Ws[64][64];   // W chunk: [k][col]

    const int t    = threadIdx.x;
    const int row0 = blockIdx.x * 64;

    const float* src;
    float* dst;
    int roff;
    if (row0 < ROWS) { src = query; dst = g_q;  roff = row0; }
    else             { src = value; dst = g_kv; roff = row0 - ROWS; }

    const int trow = t >> 4;        // 0..15 -> rows trow*4..+3
    const int tcol = t & 15;        // 0..15 -> cols tcol*4..+3
    const int lrow = t >> 2;        // 0..63 loader row
    const int lseg = (t & 3) * 16;  // loader k-segment

    float acc[4][4];
#pragma unroll
    for (int r = 0; r < 4; r++)
#pragma unroll
        for (int c = 0; c < 4; c++) acc[r][c] = 0.0f;

    for (int k0 = 0; k0 < DIM; k0 += 64) {
        // load A chunk (64 rows x 64 k), store transposed
        const float* ap = src + (size_t)(roff + lrow) * DIM + k0 + lseg;
#pragma unroll
        for (int v = 0; v < 4; v++) {
            float4 x = reinterpret_cast<const float4*>(ap)[v];
            int kk = lseg + v * 4;
            At[kk + 0][lrow] = x.x;
            At[kk + 1][lrow] = x.y;
            At[kk + 2][lrow] = x.z;
            At[kk + 3][lrow] = x.w;
        }
        // load W chunk (64 k x 64 cols) row-major
        const float* wp = Wi + (size_t)(k0 + lrow) * DK + lseg;
#pragma unroll
        for (int v = 0; v < 4; v++) {
            reinterpret_cast<float4*>(&Ws[lrow][lseg])[v] =
                reinterpret_cast<const float4*>(wp)[v];
        }
        __syncthreads();

#pragma unroll 16
        for (int kk = 0; kk < 64; kk++) {
            float4 a = *reinterpret_cast<const float4*>(&At[kk][trow * 4]);
            float4 b = *reinterpret_cast<const float4*>(&Ws[kk][tcol * 4]);
            float av[4] = {a.x, a.y, a.z, a.w};
            float bv[4] = {b.x, b.y, b.z, b.w};
#pragma unroll
            for (int r = 0; r < 4; r++)
#pragma unroll
                for (int c = 0; c < 4; c++) acc[r][c] += av[r] * bv[c];
        }
        __syncthreads();
    }

    float4 bb = *reinterpret_cast<const float4*>(&bi[tcol * 4]);
#pragma unroll
    for (int r = 0; r < 4; r++) {
        float4 o;
        o.x = acc[r][0] + bb.x;
        o.y = acc[r][1] + bb.y;
        o.z = acc[r][2] + bb.z;
        o.w = acc[r][3] + bb.w;
        *reinterpret_cast<float4*>(&dst[(size_t)(roff + trow * 4 + r) * DK + tcol * 4]) = o;
    }
}

// ---------------------------------------------------------------------------
// Kernel 2: banded attention.
//   att[i,:] = sum_{|i-j|<=128} (q_i . kv_j) * SCALE * kv_j
// Block = one (batch, 128-row q tile). Only k-tiles {t-1,t,t+1} intersect band.
// Dynamic smem: qT[64][132] | kvT[64][132] | kvR[128][68] | S[128][129]
// ---------------------------------------------------------------------------
#define SM_QT   0
#define SM_KVT  (64*132)
#define SM_KVR  (2*64*132)
#define SM_S    (2*64*132 + 128*68)
#define ATTN_SMEM_FLOATS (2*64*132 + 128*68 + 128*129)

__global__ void __launch_bounds__(256) attn_kernel()
{
    extern __shared__ float sm[];
    float (*qT)[132]  = reinterpret_cast<float(*)[132]>(sm + SM_QT);
    float (*kvT)[132] = reinterpret_cast<float(*)[132]>(sm + SM_KVT);
    float (*kvR)[68]  = reinterpret_cast<float(*)[68]>(sm + SM_KVR);
    float (*Ssm)[129] = reinterpret_cast<float(*)[129]>(sm + SM_S);

    const int t  = threadIdx.x;
    const int b  = blockIdx.x >> 5;   // batch
    const int qt = blockIdx.x & 31;   // q tile within seq (32 tiles of 128)
    const int qbase = qt * 128;

    const int lr = t >> 1;            // loader row 0..127
    const int lh = (t & 1) * 32;      // loader half of DK

    // load q tile transposed
    const float* qg = g_q + ((size_t)b * SEQ + qbase) * DK;
#pragma unroll
    for (int v = 0; v < 8; v++) {
        float4 x = reinterpret_cast<const float4*>(qg + (size_t)lr * DK + lh)[v];
        int k = lh + v * 4;
        qT[k + 0][lr] = x.x;
        qT[k + 1][lr] = x.y;
        qT[k + 2][lr] = x.z;
        qT[k + 3][lr] = x.w;
    }

    const int arow = t >> 4, acol = t & 15;   // phase A: 8x8 of S
    const int brow = t >> 3, bcol = t & 7;    // phase B: 4 rows x 8 cols of att

    float acc[4][8];
#pragma unroll
    for (int r = 0; r < 4; r++)
#pragma unroll
        for (int c = 0; c < 8; c++) acc[r][c] = 0.0f;

    for (int kt = qt - 1; kt <= qt + 1; kt++) {
        if (kt < 0 || kt >= 32) continue;
        __syncthreads();   // protect kv tiles from previous iteration / q stores

        const float* kg = g_kv + ((size_t)b * SEQ + kt * 128) * DK;
#pragma unroll
        for (int v = 0; v < 8; v++) {
            float4 x = reinterpret_cast<const float4*>(kg + (size_t)lr * DK + lh)[v];
            int k = lh + v * 4;
            kvT[k + 0][lr] = x.x;
            kvT[k + 1][lr] = x.y;
            kvT[k + 2][lr] = x.z;
            kvT[k + 3][lr] = x.w;
            reinterpret_cast<float4*>(&kvR[lr][lh])[v] = x;
        }
        __syncthreads();

        // ---- Phase A: S[i][j] = mask * SCALE * dot(q_i, kv_j) ----
        const int i0 = arow * 8, j0 = acol * 8;
        float s[8][8];
#pragma unroll
        for (int r = 0; r < 8; r++)
#pragma unroll
            for (int c = 0; c < 8; c++) s[r][c] = 0.0f;

#pragma unroll 8
        for (int k = 0; k < DK; k++) {
            float4 a0 = *reinterpret_cast<const float4*>(&qT[k][i0]);
            float4 a1 = *reinterpret_cast<const float4*>(&qT[k][i0 + 4]);
            float4 b0 = *reinterpret_cast<const float4*>(&kvT[k][j0]);
            float4 b1 = *reinterpret_cast<const float4*>(&kvT[k][j0 + 4]);
            float av[8] = {a0.x, a0.y, a0.z, a0.w, a1.x, a1.y, a1.z, a1.w};
            float bv[8] = {b0.x, b0.y, b0.z, b0.w, b1.x, b1.y, b1.z, b1.w};
#pragma unroll
            for (int r = 0; r < 8; r++)
#pragma unroll
                for (int c = 0; c < 8; c++) s[r][c] += av[r] * bv[c];
        }

        const int kbase = kt * 128;
#pragma unroll
        for (int r = 0; r < 8; r++) {
            int gi = qbase + i0 + r;
#pragma unroll
            for (int c = 0; c < 8; c++) {
                int gj = kbase + j0 + c;
                int d = gi - gj;
                Ssm[i0 + r][j0 + c] = (d <= BAND && d >= -BAND) ? s[r][c] * SCALE : 0.0f;
            }
        }
        __syncthreads();

        // ---- Phase B: acc[i][d] += sum_j S[i][j] * kv[j][d] ----
        const int ib = brow * 4, d0 = bcol * 8;
#pragma unroll 4
        for (int j = 0; j < 128; j++) {
            float s0 = Ssm[ib + 0][j];
            float s1 = Ssm[ib + 1][j];
            float s2 = Ssm[ib + 2][j];
            float s3 = Ssm[ib + 3][j];
            float4 v0 = *reinterpret_cast<const float4*>(&kvR[j][d0]);
            float4 v1 = *reinterpret_cast<const float4*>(&kvR[j][d0 + 4]);
            float vv[8] = {v0.x, v0.y, v0.z, v0.w, v1.x, v1.y, v1.z, v1.w};
            float sv[4] = {s0, s1, s2, s3};
#pragma unroll
            for (int r = 0; r < 4; r++)
#pragma unroll
                for (int c = 0; c < 8; c++) acc[r][c] += sv[r] * vv[c];
        }
    }

    // store att tile
    float* og = g_att + ((size_t)b * SEQ + qbase) * DK;
    const int ib = brow * 4, d0 = bcol * 8;
#pragma unroll
    for (int r = 0; r < 4; r++) {
        float4 o0 = {acc[r][0], acc[r][1], acc[r][2], acc[r][3]};
        float4 o1 = {acc[r][4], acc[r][5], acc[r][6], acc[r][7]};
        float* p = og + (size_t)(ib + r) * DK + d0;
        reinterpret_cast<float4*>(p)[0] = o0;
        reinterpret_cast<float4*>(p)[1] = o1;
    }
}

// ---------------------------------------------------------------------------
// Kernel 3: out = att @ Wo + bo    [16384,64]x[64,512]
// Block: 64 rows x 128 cols, 256 threads, 4x8 micro-tile. K=64 single pass.
// Dynamic smem: attT[64][68] | WoS[64][128]
// ---------------------------------------------------------------------------
#define OUT_SMEM_FLOATS (64*68 + 64*128)

__global__ void __launch_bounds__(256) out_kernel(const float* __restrict__ Wo,
                                                  const float* __restrict__ bo,
                                                  float* __restrict__ out)
{
    extern __shared__ float sm[];
    float (*attT)[68] = reinterpret_cast<float(*)[68]>(sm);
    float (*WoS)[128] = reinterpret_cast<float(*)[128]>(sm + 64 * 68);

    const int t    = threadIdx.x;
    const int rb   = blockIdx.x >> 2;
    const int cb   = blockIdx.x & 3;
    const int row0 = rb * 64;
    const int col0 = cb * 128;

    // load att tile transposed (64x64)
    {
        int lrow = t >> 2;
        int lseg = (t & 3) * 16;
        const float* ap = g_att + (size_t)(row0 + lrow) * DK + lseg;
#pragma unroll
        for (int v = 0; v < 4; v++) {
            float4 x = reinterpret_cast<const float4*>(ap)[v];
            int kk = lseg + v * 4;
            attT[kk + 0][lrow] = x.x;
            attT[kk + 1][lrow] = x.y;
            attT[kk + 2][lrow] = x.z;
            attT[kk + 3][lrow] = x.w;
        }
    }
    // load Wo tile (64 x 128)
    {
        int wk   = t >> 2;
        int wseg = (t & 3) * 32;
        const float* wp = Wo + (size_t)wk * DIM + col0 + wseg;
#pragma unroll
        for (int v = 0; v < 8; v++) {
            reinterpret_cast<float4*>(&WoS[wk][wseg])[v] =
                reinterpret_cast<const float4*>(wp)[v];
        }
    }
    __syncthreads();

    const int trow = t >> 4;   // rows trow*4..+3
    const int tcol = t & 15;   // cols tcol*8..+7
    float acc[4][8];
#pragma unroll
    for (int r = 0; r < 4; r++)
#pragma unroll
        for (int c = 0; c < 8; c++) acc[r][c] = 0.0f;

#pragma unroll 8
    for (int k = 0; k < DK; k++) {
        float4 a  = *reinterpret_cast<const float4*>(&attT[k][trow * 4]);
        float4 b0 = *reinterpret_cast<const float4*>(&WoS[k][tcol * 8]);
        float4 b1 = *reinterpret_cast<const float4*>(&WoS[k][tcol * 8 + 4]);
        float av[4] = {a.x, a.y, a.z, a.w};
        float bv[8] = {b0.x, b0.y, b0.z, b0.w, b1.x, b1.y, b1.z, b1.w};
#pragma unroll
        for (int r = 0; r < 4; r++)
#pragma unroll
            for (int c = 0; c < 8; c++) acc[r][c] += av[r] * bv[c];
    }

    float4 bb0 = *reinterpret_cast<const float4*>(&bo[col0 + tcol * 8]);
    float4 bb1 = *reinterpret_cast<const float4*>(&bo[col0 + tcol * 8 + 4]);
    float bbv[8] = {bb0.x, bb0.y, bb0.z, bb0.w, bb1.x, bb1.y, bb1.z, bb1.w};

#pragma unroll
    for (int r = 0; r < 4; r++) {
        float* p = out + (size_t)(row0 + trow * 4 + r) * DIM + col0 + tcol * 8;
        float4 o0 = {acc[r][0] + bbv[0], acc[r][1] + bbv[1],
                     acc[r][2] + bbv[2], acc[r][3] + bbv[3]};
        float4 o1 = {acc[r][4] + bbv[4], acc[r][5] + bbv[5],
                     acc[r][6] + bbv[6], acc[r][7] + bbv[7]};
        reinterpret_cast<float4*>(p)[0] = o0;
        reinterpret_cast<float4*>(p)[1] = o1;
    }
}

// ---------------------------------------------------------------------------
extern "C" void kernel_launch(void* const* d_in, const int* in_sizes, int n_in,
                              void* d_out, int out_size)
{
    const float* query = (const float*)d_in[0];
    const float* value = (const float*)d_in[1];
    const float* Wi    = (const float*)d_in[2];
    const float* bi    = (const float*)d_in[3];
    const float* Wo    = (const float*)d_in[4];
    const float* bo    = (const float*)d_in[5];
    float* out = (float*)d_out;

    static bool attr_set = false;
    if (!attr_set) {
        cudaFuncSetAttribute(attn_kernel, cudaFuncAttributeMaxDynamicSharedMemorySize,
                             ATTN_SMEM_FLOATS * (int)sizeof(float));
        cudaFuncSetAttribute(out_kernel, cudaFuncAttributeMaxDynamicSharedMemorySize,
                             OUT_SMEM_FLOATS * (int)sizeof(float));
        attr_set = true;
    }

    proj_kernel<<<MTOT / 64, 256>>>(query, value, Wi, bi);
    attn_kernel<<<BATCH * (SEQ / 128), 256, ATTN_SMEM_FLOATS * (int)sizeof(float)>>>();
    out_kernel<<<(ROWS / 64) * (DIM / 128), 256, OUT_SMEM_FLOATS * (int)sizeof(float)>>>(Wo, bo, out);
}

// round 4
// speedup vs baseline: 1.2182x; 1.2182x over previous
#include <cuda_runtime.h>
#include <cuda_bf16.h>

// Problem constants (fixed by dataset)
#define BATCH 4
#define SEQ   4096
#define DIM   512
#define DK    64
#define BAND  128
#define SCALE 0.125f            // 1/sqrt(64)
#define ROWS  (BATCH*SEQ)       // 16384
#define MTOT  (2*ROWS)          // 32768 (q rows then kv rows)

typedef unsigned long long ull;

// ---- packed f32x2 helpers (sm_100+/sm_103a) -------------------------------
__device__ __forceinline__ ull ffma2(ull a, ull b, ull c) {
    ull d;
    asm("fma.rn.f32x2 %0, %1, %2, %3;" : "=l"(d) : "l"(a), "l"(b), "l"(c));
    return d;
}
__device__ __forceinline__ ull bcast2(float x) {
    ull d;
    asm("mov.b64 %0, {%1, %1};" : "=l"(d) : "f"(x));
    return d;
}
__device__ __forceinline__ void unpack2(ull v, float& lo, float& hi) {
    asm("mov.b64 {%0, %1}, %2;" : "=f"(lo), "=f"(hi) : "l"(v));
}

// Scratch (device globals; no allocation allowed)
__device__ float g_q[ROWS * DK];
__device__ float g_kv[ROWS * DK];
__device__ float g_att[ROWS * DK];

// ---------------------------------------------------------------------------
// Kernel 1: shared input projection.  dst = src @ Wi + bi
// 32768 rows total (query rows then value rows), N=64, K=512.
// Block: 256 rows x 64 cols, 256 threads, 8x8 micro-tile, f32x2 FMA.
// ---------------------------------------------------------------------------
__global__ void __launch_bounds__(256) proj_kernel(const float* __restrict__ query,
                                                   const float* __restrict__ value,
                                                   const float* __restrict__ Wi,
                                                   const float* __restrict__ bi)
{
    __shared__ __align__(16) float At[32][264];   // A chunk transposed: [k][row]
    __shared__ __align__(16) float Ws[32][64];    // W chunk: [k][col]

    const int t    = threadIdx.x;
    const int row0 = blockIdx.x * 256;

    const float* src;
    float* dst;
    int roff;
    if (row0 < ROWS) { src = query; dst = g_q;  roff = row0; }
    else             { src = value; dst = g_kv; roff = row0 - ROWS; }

    const int trow = t >> 3;        // 0..31 -> rows trow*8..+7
    const int tcol = t & 7;         // 0..7  -> cols tcol*8..+7
    const int r0 = trow * 8, c0 = tcol * 8;

    ull acc[8][4];
#pragma unroll
    for (int r = 0; r < 8; r++)
#pragma unroll
        for (int c = 0; c < 4; c++) acc[r][c] = 0ull;

    for (int k0 = 0; k0 < DIM; k0 += 32) {
        __syncthreads();
        // A chunk: thread t loads its full row (32 floats), store transposed
        {
            const float4* ap = reinterpret_cast<const float4*>(src + (size_t)(roff + t) * DIM + k0);
#pragma unroll
            for (int v = 0; v < 8; v++) {
                float4 x = ap[v];
                int kk = v * 4;
                At[kk + 0][t] = x.x;
                At[kk + 1][t] = x.y;
                At[kk + 2][t] = x.z;
                At[kk + 3][t] = x.w;
            }
        }
        // W chunk: 32x64 floats = 512 float4, 2 per thread
        {
            const float4* wp = reinterpret_cast<const float4*>(Wi + (size_t)k0 * DK);
            int f0 = t, f1 = t + 256;
            *reinterpret_cast<float4*>(&Ws[f0 >> 4][(f0 & 15) * 4]) = wp[f0];
            *reinterpret_cast<float4*>(&Ws[f1 >> 4][(f1 & 15) * 4]) = wp[f1];
        }
        __syncthreads();

#pragma unroll
        for (int kk = 0; kk < 32; kk++) {
            float4 a0 = *reinterpret_cast<const float4*>(&At[kk][r0]);
            float4 a1 = *reinterpret_cast<const float4*>(&At[kk][r0 + 4]);
            ull pa[8];
            pa[0] = bcast2(a0.x); pa[1] = bcast2(a0.y);
            pa[2] = bcast2(a0.z); pa[3] = bcast2(a0.w);
            pa[4] = bcast2(a1.x); pa[5] = bcast2(a1.y);
            pa[6] = bcast2(a1.z); pa[7] = bcast2(a1.w);
            ulonglong2 bA = *reinterpret_cast<const ulonglong2*>(&Ws[kk][c0]);
            ulonglong2 bB = *reinterpret_cast<const ulonglong2*>(&Ws[kk][c0 + 4]);
#pragma unroll
            for (int r = 0; r < 8; r++) {
                acc[r][0] = ffma2(pa[r], bA.x, acc[r][0]);
                acc[r][1] = ffma2(pa[r], bA.y, acc[r][1]);
                acc[r][2] = ffma2(pa[r], bB.x, acc[r][2]);
                acc[r][3] = ffma2(pa[r], bB.y, acc[r][3]);
            }
        }
    }

    float bb[8];
#pragma unroll
    for (int c = 0; c < 8; c++) bb[c] = bi[c0 + c];

#pragma unroll
    for (int r = 0; r < 8; r++) {
        float v[8];
        unpack2(acc[r][0], v[0], v[1]);
        unpack2(acc[r][1], v[2], v[3]);
        unpack2(acc[r][2], v[4], v[5]);
        unpack2(acc[r][3], v[6], v[7]);
        float4 o0 = {v[0] + bb[0], v[1] + bb[1], v[2] + bb[2], v[3] + bb[3]};
        float4 o1 = {v[4] + bb[4], v[5] + bb[5], v[6] + bb[6], v[7] + bb[7]};
        float* p = dst + (size_t)(roff + r0 + r) * DK + c0;
        reinterpret_cast<float4*>(p)[0] = o0;
        reinterpret_cast<float4*>(p)[1] = o1;
    }
}

// ---------------------------------------------------------------------------
// Kernel 2: banded attention.
//   att[i,:] = sum_{|i-j|<=128} (q_i . kv_j) * SCALE * kv_j
// Block = one (batch, 128-row q tile). Only k-tiles {t-1,t,t+1} intersect band.
// Dynamic smem: qT[64][132] | kvT[64][132] | kvR[128][68] | S[128][129]
// ---------------------------------------------------------------------------
#define SM_QT   0
#define SM_KVT  (64*132)
#define SM_KVR  (2*64*132)
#define SM_S    (2*64*132 + 128*68)
#define ATTN_SMEM_FLOATS (2*64*132 + 128*68 + 128*129)

__global__ void __launch_bounds__(256) attn_kernel()
{
    extern __shared__ __align__(16) float sm[];
    float (*qT)[132]  = reinterpret_cast<float(*)[132]>(sm + SM_QT);
    float (*kvT)[132] = reinterpret_cast<float(*)[132]>(sm + SM_KVT);
    float (*kvR)[68]  = reinterpret_cast<float(*)[68]>(sm + SM_KVR);
    float (*Ssm)[129] = reinterpret_cast<float(*)[129]>(sm + SM_S);

    const int t  = threadIdx.x;
    const int b  = blockIdx.x >> 5;   // batch
    const int qt = blockIdx.x & 31;   // q tile within seq (32 tiles of 128)
    const int qbase = qt * 128;

    const int lr = t >> 1;            // loader row 0..127
    const int lh = (t & 1) * 32;      // loader half of DK

    // load q tile transposed
    const float* qg = g_q + ((size_t)b * SEQ + qbase) * DK;
#pragma unroll
    for (int v = 0; v < 8; v++) {
        float4 x = reinterpret_cast<const float4*>(qg + (size_t)lr * DK + lh)[v];
        int k = lh + v * 4;
        qT[k + 0][lr] = x.x;
        qT[k + 1][lr] = x.y;
        qT[k + 2][lr] = x.z;
        qT[k + 3][lr] = x.w;
    }

    const int arow = t >> 4, acol = t & 15;   // phase A: 8x8 subtile of S
    const int brow = t >> 3, bcol = t & 7;    // phase B: 4 rows x 8 cols of att
    const int i0 = arow * 8, j0 = acol * 8;
    const int ib = brow * 4, d0 = bcol * 8;

    ull bacc[4][4];
#pragma unroll
    for (int r = 0; r < 4; r++)
#pragma unroll
        for (int c = 0; c < 4; c++) bacc[r][c] = 0ull;

    for (int kt = qt - 1; kt <= qt + 1; kt++) {
        if (kt < 0 || kt >= 32) continue;
        __syncthreads();   // protect kv tiles / S from previous iteration

        const float* kg = g_kv + ((size_t)b * SEQ + kt * 128) * DK;
#pragma unroll
        for (int v = 0; v < 8; v++) {
            float4 x = reinterpret_cast<const float4*>(kg + (size_t)lr * DK + lh)[v];
            int k = lh + v * 4;
            kvT[k + 0][lr] = x.x;
            kvT[k + 1][lr] = x.y;
            kvT[k + 2][lr] = x.z;
            kvT[k + 3][lr] = x.w;
            reinterpret_cast<float4*>(&kvR[lr][lh])[v] = x;
        }
        __syncthreads();

        // ---- Phase A: S[i][j] = mask * SCALE * dot(q_i, kv_j) ----
        ull sacc[8][4];
#pragma unroll
        for (int r = 0; r < 8; r++)
#pragma unroll
            for (int c = 0; c < 4; c++) sacc[r][c] = 0ull;

#pragma unroll 8
        for (int k = 0; k < DK; k++) {
            float4 a0 = *reinterpret_cast<const float4*>(&qT[k][i0]);
            float4 a1 = *reinterpret_cast<const float4*>(&qT[k][i0 + 4]);
            ull pa[8];
            pa[0] = bcast2(a0.x); pa[1] = bcast2(a0.y);
            pa[2] = bcast2(a0.z); pa[3] = bcast2(a0.w);
            pa[4] = bcast2(a1.x); pa[5] = bcast2(a1.y);
            pa[6] = bcast2(a1.z); pa[7] = bcast2(a1.w);
            ulonglong2 b0 = *reinterpret_cast<const ulonglong2*>(&kvT[k][j0]);
            ulonglong2 b1 = *reinterpret_cast<const ulonglong2*>(&kvT[k][j0 + 4]);
#pragma unroll
            for (int r = 0; r < 8; r++) {
                sacc[r][0] = ffma2(pa[r], b0.x, sacc[r][0]);
                sacc[r][1] = ffma2(pa[r], b0.y, sacc[r][1]);
                sacc[r][2] = ffma2(pa[r], b1.x, sacc[r][2]);
                sacc[r][3] = ffma2(pa[r], b1.y, sacc[r][3]);
            }
        }

        const int kbase = kt * 128;
#pragma unroll
        for (int r = 0; r < 8; r++) {
            int gi = qbase + i0 + r;
            float v[8];
            unpack2(sacc[r][0], v[0], v[1]);
            unpack2(sacc[r][1], v[2], v[3]);
            unpack2(sacc[r][2], v[4], v[5]);
            unpack2(sacc[r][3], v[6], v[7]);
#pragma unroll
            for (int c = 0; c < 8; c++) {
                int gj = kbase + j0 + c;
                int d = gi - gj;
                Ssm[i0 + r][j0 + c] = (d <= BAND && d >= -BAND) ? v[c] * SCALE : 0.0f;
            }
        }
        __syncthreads();

        // ---- Phase B: acc[i][d] += sum_j S[i][j] * kv[j][d] ----
#pragma unroll 4
        for (int j = 0; j < 128; j++) {
            ull ps[4];
            ps[0] = bcast2(Ssm[ib + 0][j]);
            ps[1] = bcast2(Ssm[ib + 1][j]);
            ps[2] = bcast2(Ssm[ib + 2][j]);
            ps[3] = bcast2(Ssm[ib + 3][j]);
            ulonglong2 v0 = *reinterpret_cast<const ulonglong2*>(&kvR[j][d0]);
            ulonglong2 v1 = *reinterpret_cast<const ulonglong2*>(&kvR[j][d0 + 4]);
#pragma unroll
            for (int r = 0; r < 4; r++) {
                bacc[r][0] = ffma2(ps[r], v0.x, bacc[r][0]);
                bacc[r][1] = ffma2(ps[r], v0.y, bacc[r][1]);
                bacc[r][2] = ffma2(ps[r], v1.x, bacc[r][2]);
                bacc[r][3] = ffma2(ps[r], v1.y, bacc[r][3]);
            }
        }
    }

    // store att tile
    float* og = g_att + ((size_t)b * SEQ + qbase) * DK;
#pragma unroll
    for (int r = 0; r < 4; r++) {
        float v[8];
        unpack2(bacc[r][0], v[0], v[1]);
        unpack2(bacc[r][1], v[2], v[3]);
        unpack2(bacc[r][2], v[4], v[5]);
        unpack2(bacc[r][3], v[6], v[7]);
        float4 o0 = {v[0], v[1], v[2], v[3]};
        float4 o1 = {v[4], v[5], v[6], v[7]};
        float* p = og + (size_t)(ib + r) * DK + d0;
        reinterpret_cast<float4*>(p)[0] = o0;
        reinterpret_cast<float4*>(p)[1] = o1;
    }
}

// ---------------------------------------------------------------------------
// Kernel 3: out = att @ Wo + bo    [16384,64]x[64,512]
// Block: 128 rows x 128 cols, 256 threads, 8x8 micro-tile, f32x2 FMA.
// Dynamic smem: attT[64][132] | WoS[64][128]
// ---------------------------------------------------------------------------
#define OUT_SMEM_FLOATS (64*132 + 64*128)

__global__ void __launch_bounds__(256) out_kernel(const float* __restrict__ Wo,
                                                  const float* __restrict__ bo,
                                                  float* __restrict__ out)
{
    extern __shared__ __align__(16) float smo[];
    float (*attT)[132] = reinterpret_cast<float(*)[132]>(smo);
    float (*WoS)[128]  = reinterpret_cast<float(*)[128]>(smo + 64 * 132);

    const int t    = threadIdx.x;
    const int rb   = blockIdx.x >> 2;
    const int cb   = blockIdx.x & 3;
    const int row0 = rb * 128;
    const int col0 = cb * 128;

    // load att tile transposed (128 rows x 64 k)
    {
        int lrow = t >> 1;
        int lh   = (t & 1) * 32;
        const float* ap = g_att + (size_t)(row0 + lrow) * DK + lh;
#pragma unroll
        for (int v = 0; v < 8; v++) {
            float4 x = reinterpret_cast<const float4*>(ap)[v];
            int kk = lh + v * 4;
            attT[kk + 0][lrow] = x.x;
            attT[kk + 1][lrow] = x.y;
            attT[kk + 2][lrow] = x.z;
            attT[kk + 3][lrow] = x.w;
        }
    }
    // load Wo tile (64 k x 128 cols): 2048 float4, 8 per thread
    {
#pragma unroll
        for (int v = 0; v < 8; v++) {
            int f = v * 256 + t;
            int wk = f >> 5;
            int wc = (f & 31) * 4;
            *reinterpret_cast<float4*>(&WoS[wk][wc]) =
                *reinterpret_cast<const float4*>(Wo + (size_t)wk * DIM + col0 + wc);
        }
    }
    __syncthreads();

    const int trow = t >> 4;   // 0..15 -> rows trow*8..+7
    const int tcol = t & 15;   // 0..15 -> cols tcol*8..+7
    const int r0 = trow * 8, c0 = tcol * 8;

    ull acc[8][4];
#pragma unroll
    for (int r = 0; r < 8; r++)
#pragma unroll
        for (int c = 0; c < 4; c++) acc[r][c] = 0ull;

#pragma unroll 8
    for (int k = 0; k < DK; k++) {
        float4 a0 = *reinterpret_cast<const float4*>(&attT[k][r0]);
        float4 a1 = *reinterpret_cast<const float4*>(&attT[k][r0 + 4]);
        ull pa[8];
        pa[0] = bcast2(a0.x); pa[1] = bcast2(a0.y);
        pa[2] = bcast2(a0.z); pa[3] = bcast2(a0.w);
        pa[4] = bcast2(a1.x); pa[5] = bcast2(a1.y);
        pa[6] = bcast2(a1.z); pa[7] = bcast2(a1.w);
        ulonglong2 b0 = *reinterpret_cast<const ulonglong2*>(&WoS[k][c0]);
        ulonglong2 b1 = *reinterpret_cast<const ulonglong2*>(&WoS[k][c0 + 4]);
#pragma unroll
        for (int r = 0; r < 8; r++) {
            acc[r][0] = ffma2(pa[r], b0.x, acc[r][0]);
            acc[r][1] = ffma2(pa[r], b0.y, acc[r][1]);
            acc[r][2] = ffma2(pa[r], b1.x, acc[r][2]);
            acc[r][3] = ffma2(pa[r], b1.y, acc[r][3]);
        }
    }

    float bb[8];
#pragma unroll
    for (int c = 0; c < 8; c++) bb[c] = bo[col0 + c0 + c];

#pragma unroll
    for (int r = 0; r < 8; r++) {
        float v[8];
        unpack2(acc[r][0], v[0], v[1]);
        unpack2(acc[r][1], v[2], v[3]);
        unpack2(acc[r][2], v[4], v[5]);
        unpack2(acc[r][3], v[6], v[7]);
        float4 o0 = {v[0] + bb[0], v[1] + bb[1], v[2] + bb[2], v[3] + bb[3]};
        float4 o1 = {v[4] + bb[4], v[5] + bb[5], v[6] + bb[6], v[7] + bb[7]};
        float* p = out + (size_t)(row0 + r0 + r) * DIM + col0 + c0;
        reinterpret_cast<float4*>(p)[0] = o0;
        reinterpret_cast<float4*>(p)[1] = o1;
    }
}

// ---------------------------------------------------------------------------
extern "C" void kernel_launch(void* const* d_in, const int* in_sizes, int n_in,
                              void* d_out, int out_size)
{
    const float* query = (const float*)d_in[0];
    const float* value = (const float*)d_in[1];
    const float* Wi    = (const float*)d_in[2];
    const float* bi    = (const float*)d_in[3];
    const float* Wo    = (const float*)d_in[4];
    const float* bo    = (const float*)d_in[5];
    float* out = (float*)d_out;

    static bool attr_set = false;
    if (!attr_set) {
        cudaFuncSetAttribute(attn_kernel, cudaFuncAttributeMaxDynamicSharedMemorySize,
                             ATTN_SMEM_FLOATS * (int)sizeof(float));
        cudaFuncSetAttribute(out_kernel, cudaFuncAttributeMaxDynamicSharedMemorySize,
                             OUT_SMEM_FLOATS * (int)sizeof(float));
        attr_set = true;
    }

    proj_kernel<<<MTOT / 256, 256>>>(query, value, Wi, bi);
    attn_kernel<<<BATCH * (SEQ / 128), 256, ATTN_SMEM_FLOATS * (int)sizeof(float)>>>();
    out_kernel<<<(ROWS / 128) * (DIM / 128), 256, OUT_SMEM_FLOATS * (int)sizeof(float)>>>(Wo, bo, out);
}

// round 6
// speedup vs baseline: 1.3549x; 1.1123x over previous
#include <cuda_runtime.h>
#include <cuda_bf16.h>

// Problem constants (fixed by dataset)
#define BATCH 4
#define SEQ   4096
#define DIM   512
#define DK    64
#define BAND  128
#define SCALE 0.125f            // 1/sqrt(64)
#define ROWS  (BATCH*SEQ)       // 16384
#define MTOT  (2*ROWS)          // 32768 (q rows then kv rows)

typedef unsigned long long ull;

// ---- packed f32x2 helpers (sm_100+/sm_103a) -------------------------------
__device__ __forceinline__ ull ffma2(ull a, ull b, ull c) {
    ull d;
    asm("fma.rn.f32x2 %0, %1, %2, %3;" : "=l"(d) : "l"(a), "l"(b), "l"(c));
    return d;
}
__device__ __forceinline__ ull bcast2(float x) {
    ull d;
    asm("mov.b64 %0, {%1, %1};" : "=l"(d) : "f"(x));
    return d;
}
__device__ __forceinline__ void unpack2(ull v, float& lo, float& hi) {
    asm("mov.b64 {%0, %1}, %2;" : "=f"(lo), "=f"(hi) : "l"(v));
}

// Scratch (device globals; no allocation allowed)
__device__ float g_q[ROWS * DK];
__device__ float g_kv[ROWS * DK];
__device__ float g_att[ROWS * DK];

// ---------------------------------------------------------------------------
// Kernel 1: shared input projection.  dst = src @ Wi + bi
// 32768 rows total (query rows then value rows), N=64, K=512.
// Block: 128 rows x 64 cols, 256 threads, 8x4 micro-tile, f32x2 FMA.
// grid = 256 -> ~2 CTAs/SM (16 warps) for latency hiding.
// ---------------------------------------------------------------------------
__global__ void __launch_bounds__(256) proj_kernel(const float* __restrict__ query,
                                                   const float* __restrict__ value,
                                                   const float* __restrict__ Wi,
                                                   const float* __restrict__ bi)
{
    __shared__ __align__(16) float At[32][132];   // A chunk transposed: [k][row]
    __shared__ __align__(16) float Ws[32][64];    // W chunk: [k][col]

    const int t    = threadIdx.x;
    const int row0 = blockIdx.x * 128;

    const float* src;
    float* dst;
    int roff;
    if (row0 < ROWS) { src = query; dst = g_q;  roff = row0; }
    else             { src = value; dst = g_kv; roff = row0 - ROWS; }

    const int trow = t >> 4;        // 0..15 -> rows trow*8..+7
    const int tcol = t & 15;        // 0..15 -> cols tcol*4..+3
    const int r0 = trow * 8, c0 = tcol * 4;

    const int lr = t >> 1;          // loader row 0..127
    const int lh = (t & 1) * 16;    // loader k-half (16 floats)

    ull acc[8][2];
#pragma unroll
    for (int r = 0; r < 8; r++) { acc[r][0] = 0ull; acc[r][1] = 0ull; }

    for (int k0 = 0; k0 < DIM; k0 += 32) {
        __syncthreads();
        // A chunk: 128 rows x 32 k, store transposed
        {
            const float4* ap = reinterpret_cast<const float4*>(
                src + (size_t)(roff + lr) * DIM + k0 + lh);
#pragma unroll
            for (int v = 0; v < 4; v++) {
                float4 x = ap[v];
                int kk = lh + v * 4;
                At[kk + 0][lr] = x.x;
                At[kk + 1][lr] = x.y;
                At[kk + 2][lr] = x.z;
                At[kk + 3][lr] = x.w;
            }
        }
        // W chunk: 32x64 floats = 512 float4, 2 per thread
        {
            const float4* wp = reinterpret_cast<const float4*>(Wi + (size_t)k0 * DK);
            int f0 = t, f1 = t + 256;
            *reinterpret_cast<float4*>(&Ws[f0 >> 4][(f0 & 15) * 4]) = wp[f0];
            *reinterpret_cast<float4*>(&Ws[f1 >> 4][(f1 & 15) * 4]) = wp[f1];
        }
        __syncthreads();

#pragma unroll
        for (int kk = 0; kk < 32; kk++) {
            float4 a0 = *reinterpret_cast<const float4*>(&At[kk][r0]);
            float4 a1 = *reinterpret_cast<const float4*>(&At[kk][r0 + 4]);
            ull pa[8];
            pa[0] = bcast2(a0.x); pa[1] = bcast2(a0.y);
            pa[2] = bcast2(a0.z); pa[3] = bcast2(a0.w);
            pa[4] = bcast2(a1.x); pa[5] = bcast2(a1.y);
            pa[6] = bcast2(a1.z); pa[7] = bcast2(a1.w);
            ulonglong2 bB = *reinterpret_cast<const ulonglong2*>(&Ws[kk][c0]);
#pragma unroll
            for (int r = 0; r < 8; r++) {
                acc[r][0] = ffma2(pa[r], bB.x, acc[r][0]);
                acc[r][1] = ffma2(pa[r], bB.y, acc[r][1]);
            }
        }
    }

    float bb[4];
#pragma unroll
    for (int c = 0; c < 4; c++) bb[c] = bi[c0 + c];

#pragma unroll
    for (int r = 0; r < 8; r++) {
        float v[4];
        unpack2(acc[r][0], v[0], v[1]);
        unpack2(acc[r][1], v[2], v[3]);
        float4 o = {v[0] + bb[0], v[1] + bb[1], v[2] + bb[2], v[3] + bb[3]};
        *reinterpret_cast<float4*>(&dst[(size_t)(roff + r0 + r) * DK + c0]) = o;
    }
}

// ---------------------------------------------------------------------------
// Kernel 2: banded attention.
//   att[i,:] = sum_{|i-j|<=128} (q_i . kv_j) * SCALE * kv_j
// Block = one (batch, 64-row q tile); j-tiles of 64, jt in {qs-2..qs+2}.
// 128 threads. grid = 4*64 = 256.
// smem: qT[64][68] | kvT[64][68] | kvR[64][68] | Ssm[64][68]  (68 KB)
// ---------------------------------------------------------------------------
#define ATTN_SMEM_FLOATS (4*64*68)

__global__ void __launch_bounds__(128) attn_kernel()
{
    extern __shared__ __align__(16) float sm[];
    float (*qT)[68]  = reinterpret_cast<float(*)[68]>(sm);            // [k][i]
    float (*kvT)[68] = reinterpret_cast<float(*)[68]>(sm + 64 * 68);  // [k][j]
    float (*kvR)[68] = reinterpret_cast<float(*)[68]>(sm + 2 * 64 * 68); // [j][d]
    float (*Ssm)[68] = reinterpret_cast<float(*)[68]>(sm + 3 * 64 * 68); // [i][j]

    const int t  = threadIdx.x;
    const int b  = blockIdx.x >> 6;   // batch
    const int qs = blockIdx.x & 63;   // 64-row q tile index
    const int q0 = qs * 64;

    const int lr = t >> 1;            // loader row 0..63
    const int lh = (t & 1) * 32;      // loader half of DK

    // load q tile transposed
    const float* qg = g_q + ((size_t)b * SEQ + q0) * DK;
#pragma unroll
    for (int v = 0; v < 8; v++) {
        float4 x = reinterpret_cast<const float4*>(qg + (size_t)lr * DK + lh)[v];
        int k = lh + v * 4;
        qT[k + 0][lr] = x.x;
        qT[k + 1][lr] = x.y;
        qT[k + 2][lr] = x.z;
        qT[k + 3][lr] = x.w;
    }

    const int arow = t >> 4, acol = t & 15;   // phase A: 8x4 subtile of S
    const int brow = t >> 3, bcol = t & 7;    // phase B: 4 rows x 8 cols of att
    const int i0a = arow * 8, j0a = acol * 4;
    const int i0b = brow * 4, d0 = bcol * 8;

    ull bacc[4][4];
#pragma unroll
    for (int r = 0; r < 4; r++)
#pragma unroll
        for (int c = 0; c < 4; c++) bacc[r][c] = 0ull;

    for (int jt = qs - 2; jt <= qs + 2; jt++) {
        if (jt < 0 || jt >= 64) continue;
        __syncthreads();   // protect kv/S from previous iteration

        const float* kg = g_kv + ((size_t)b * SEQ + jt * 64) * DK;
#pragma unroll
        for (int v = 0; v < 8; v++) {
            float4 x = reinterpret_cast<const float4*>(kg + (size_t)lr * DK + lh)[v];
            int k = lh + v * 4;
            kvT[k + 0][lr] = x.x;
            kvT[k + 1][lr] = x.y;
            kvT[k + 2][lr] = x.z;
            kvT[k + 3][lr] = x.w;
            reinterpret_cast<float4*>(&kvR[lr][lh])[v] = x;
        }
        __syncthreads();

        // ---- Phase A: S[i][j] = mask * SCALE * dot(q_i, kv_j) ----
        ull sacc[8][2];
#pragma unroll
        for (int r = 0; r < 8; r++) { sacc[r][0] = 0ull; sacc[r][1] = 0ull; }

#pragma unroll 8
        for (int k = 0; k < DK; k++) {
            float4 a0 = *reinterpret_cast<const float4*>(&qT[k][i0a]);
            float4 a1 = *reinterpret_cast<const float4*>(&qT[k][i0a + 4]);
            ull pa[8];
            pa[0] = bcast2(a0.x); pa[1] = bcast2(a0.y);
            pa[2] = bcast2(a0.z); pa[3] = bcast2(a0.w);
            pa[4] = bcast2(a1.x); pa[5] = bcast2(a1.y);
            pa[6] = bcast2(a1.z); pa[7] = bcast2(a1.w);
            ulonglong2 bb = *reinterpret_cast<const ulonglong2*>(&kvT[k][j0a]);
#pragma unroll
            for (int r = 0; r < 8; r++) {
                sacc[r][0] = ffma2(pa[r], bb.x, sacc[r][0]);
                sacc[r][1] = ffma2(pa[r], bb.y, sacc[r][1]);
            }
        }

        const int jbase = jt * 64;
#pragma unroll
        for (int r = 0; r < 8; r++) {
            int gi = q0 + i0a + r;
            float v[4];
            unpack2(sacc[r][0], v[0], v[1]);
            unpack2(sacc[r][1], v[2], v[3]);
            float4 o;
            {
                int gj = jbase + j0a;
                int d0m = gi - gj;
                o.x = (d0m <= BAND && d0m >= -BAND) ? v[0] * SCALE : 0.0f;
                int d1m = d0m - 1;
                o.y = (d1m <= BAND && d1m >= -BAND) ? v[1] * SCALE : 0.0f;
                int d2m = d0m - 2;
                o.z = (d2m <= BAND && d2m >= -BAND) ? v[2] * SCALE : 0.0f;
                int d3m = d0m - 3;
                o.w = (d3m <= BAND && d3m >= -BAND) ? v[3] * SCALE : 0.0f;
            }
            *reinterpret_cast<float4*>(&Ssm[i0a + r][j0a]) = o;
        }
        __syncthreads();

        // ---- Phase B: acc[i][d] += sum_j S[i][j] * kv[j][d] ----
#pragma unroll 4
        for (int j = 0; j < 64; j++) {
            ull ps[4];
            ps[0] = bcast2(Ssm[i0b + 0][j]);
            ps[1] = bcast2(Ssm[i0b + 1][j]);
            ps[2] = bcast2(Ssm[i0b + 2][j]);
            ps[3] = bcast2(Ssm[i0b + 3][j]);
            ulonglong2 v0 = *reinterpret_cast<const ulonglong2*>(&kvR[j][d0]);
            ulonglong2 v1 = *reinterpret_cast<const ulonglong2*>(&kvR[j][d0 + 4]);
#pragma unroll
            for (int r = 0; r < 4; r++) {
                bacc[r][0] = ffma2(ps[r], v0.x, bacc[r][0]);
                bacc[r][1] = ffma2(ps[r], v0.y, bacc[r][1]);
                bacc[r][2] = ffma2(ps[r], v1.x, bacc[r][2]);
                bacc[r][3] = ffma2(ps[r], v1.y, bacc[r][3]);
            }
        }
    }

    // store att tile
    float* og = g_att + ((size_t)b * SEQ + q0) * DK;
#pragma unroll
    for (int r = 0; r < 4; r++) {
        float v[8];
        unpack2(bacc[r][0], v[0], v[1]);
        unpack2(bacc[r][1], v[2], v[3]);
        unpack2(bacc[r][2], v[4], v[5]);
        unpack2(bacc[r][3], v[6], v[7]);
        float4 o0 = {v[0], v[1], v[2], v[3]};
        float4 o1 = {v[4], v[5], v[6], v[7]};
        float* p = og + (size_t)(i0b + r) * DK + d0;
        reinterpret_cast<float4*>(p)[0] = o0;
        reinterpret_cast<float4*>(p)[1] = o1;
    }
}

// ---------------------------------------------------------------------------
// Kernel 3: out = att @ Wo + bo    [16384,64]x[64,512]
// Block: 128 rows x 128 cols, 256 threads, 8x8 micro-tile, f32x2 FMA.
// Dynamic smem: attT[64][132] | WoS[64][128]
// ---------------------------------------------------------------------------
#define OUT_SMEM_FLOATS (64*132 + 64*128)

__global__ void __launch_bounds__(256) out_kernel(const float* __restrict__ Wo,
                                                  const float* __restrict__ bo,
                                                  float* __restrict__ out)
{
    extern __shared__ __align__(16) float smo[];
    float (*attT)[132] = reinterpret_cast<float(*)[132]>(smo);
    float (*WoS)[128]  = reinterpret_cast<float(*)[128]>(smo + 64 * 132);

    const int t    = threadIdx.x;
    const int rb   = blockIdx.x >> 2;
    const int cb   = blockIdx.x & 3;
    const int row0 = rb * 128;
    const int col0 = cb * 128;

    // load att tile transposed (128 rows x 64 k)
    {
        int lrow = t >> 1;
        int lh   = (t & 1) * 32;
        const float* ap = g_att + (size_t)(row0 + lrow) * DK + lh;
#pragma unroll
        for (int v = 0; v < 8; v++) {
            float4 x = reinterpret_cast<const float4*>(ap)[v];
            int kk = lh + v * 4;
            attT[kk + 0][lrow] = x.x;
            attT[kk + 1][lrow] = x.y;
            attT[kk + 2][lrow] = x.z;
            attT[kk + 3][lrow] = x.w;
        }
    }
    // load Wo tile (64 k x 128 cols): 2048 float4, 8 per thread
    {
#pragma unroll
        for (int v = 0; v < 8; v++) {
            int f = v * 256 + t;
            int wk = f >> 5;
            int wc = (f & 31) * 4;
            *reinterpret_cast<float4*>(&WoS[wk][wc]) =
                *reinterpret_cast<const float4*>(Wo + (size_t)wk * DIM + col0 + wc);
        }
    }
    __syncthreads();

    const int trow = t >> 4;   // 0..15 -> rows trow*8..+7
    const int tcol = t & 15;   // 0..15 -> cols tcol*8..+7
    const int r0 = trow * 8, c0 = tcol * 8;

    ull acc[8][4];
#pragma unroll
    for (int r = 0; r < 8; r++)
#pragma unroll
        for (int c = 0; c < 4; c++) acc[r][c] = 0ull;

#pragma unroll 8
    for (int k = 0; k < DK; k++) {
        float4 a0 = *reinterpret_cast<const float4*>(&attT[k][r0]);
        float4 a1 = *reinterpret_cast<const float4*>(&attT[k][r0 + 4]);
        ull pa[8];
        pa[0] = bcast2(a0.x); pa[1] = bcast2(a0.y);
        pa[2] = bcast2(a0.z); pa[3] = bcast2(a0.w);
        pa[4] = bcast2(a1.x); pa[5] = bcast2(a1.y);
        pa[6] = bcast2(a1.z); pa[7] = bcast2(a1.w);
        ulonglong2 b0 = *reinterpret_cast<const ulonglong2*>(&WoS[k][c0]);
        ulonglong2 b1 = *reinterpret_cast<const ulonglong2*>(&WoS[k][c0 + 4]);
#pragma unroll
        for (int r = 0; r < 8; r++) {
            acc[r][0] = ffma2(pa[r], b0.x, acc[r][0]);
            acc[r][1] = ffma2(pa[r], b0.y, acc[r][1]);
            acc[r][2] = ffma2(pa[r], b1.x, acc[r][2]);
            acc[r][3] = ffma2(pa[r], b1.y, acc[r][3]);
        }
    }

    float bb[8];
#pragma unroll
    for (int c = 0; c < 8; c++) bb[c] = bo[col0 + c0 + c];

#pragma unroll
    for (int r = 0; r < 8; r++) {
        float v[8];
        unpack2(acc[r][0], v[0], v[1]);
        unpack2(acc[r][1], v[2], v[3]);
        unpack2(acc[r][2], v[4], v[5]);
        unpack2(acc[r][3], v[6], v[7]);
        float4 o0 = {v[0] + bb[0], v[1] + bb[1], v[2] + bb[2], v[3] + bb[3]};
        float4 o1 = {v[4] + bb[4], v[5] + bb[5], v[6] + bb[6], v[7] + bb[7]};
        float* p = out + (size_t)(row0 + r0 + r) * DIM + col0 + c0;
        reinterpret_cast<float4*>(p)[0] = o0;
        reinterpret_cast<float4*>(p)[1] = o1;
    }
}

// ---------------------------------------------------------------------------
extern "C" void kernel_launch(void* const* d_in, const int* in_sizes, int n_in,
                              void* d_out, int out_size)
{
    const float* query = (const float*)d_in[0];
    const float* value = (const float*)d_in[1];
    const float* Wi    = (const float*)d_in[2];
    const float* bi    = (const float*)d_in[3];
    const float* Wo    = (const float*)d_in[4];
    const float* bo    = (const float*)d_in[5];
    float* out = (float*)d_out;

    static bool attr_set = false;
    if (!attr_set) {
        cudaFuncSetAttribute(attn_kernel, cudaFuncAttributeMaxDynamicSharedMemorySize,
                             ATTN_SMEM_FLOATS * (int)sizeof(float));
        cudaFuncSetAttribute(out_kernel, cudaFuncAttributeMaxDynamicSharedMemorySize,
                             OUT_SMEM_FLOATS * (int)sizeof(float));
        attr_set = true;
    }

    proj_kernel<<<MTOT / 128, 256>>>(query, value, Wi, bi);
    attn_kernel<<<BATCH * (SEQ / 64), 128, ATTN_SMEM_FLOATS * (int)sizeof(float)>>>();
    out_kernel<<<(ROWS / 128) * (DIM / 128), 256, OUT_SMEM_FLOATS * (int)sizeof(float)>>>(Wo, bo, out);
}

// round 7
// speedup vs baseline: 1.6355x; 1.2071x over previous
#include <cuda_runtime.h>
#include <cuda_bf16.h>
#include <cstdint>

// Problem constants (fixed by dataset)
#define BATCH 4
#define SEQ   4096
#define DIM   512
#define DK    64
#define BAND  128
#define SCALE 0.125f            // 1/sqrt(64)
#define ROWS  (BATCH*SEQ)       // 16384
#define MTOT  (2*ROWS)          // 32768 (q rows then kv rows)

typedef unsigned long long ull;

// ---- packed f32x2 helpers (sm_100+/sm_103a) -------------------------------
__device__ __forceinline__ ull ffma2(ull a, ull b, ull c) {
    ull d;
    asm("fma.rn.f32x2 %0, %1, %2, %3;" : "=l"(d) : "l"(a), "l"(b), "l"(c));
    return d;
}
__device__ __forceinline__ ull bcast2(float x) {
    ull d;
    asm("mov.b64 %0, {%1, %1};" : "=l"(d) : "f"(x));
    return d;
}
__device__ __forceinline__ void unpack2(ull v, float& lo, float& hi) {
    asm("mov.b64 {%0, %1}, %2;" : "=f"(lo), "=f"(hi) : "l"(v));
}

// ---- tensor-core helpers ---------------------------------------------------
#define LDSM_X4(r0, r1, r2, r3, addr) \
    asm volatile("ldmatrix.sync.aligned.m8n8.x4.shared.b16 {%0,%1,%2,%3}, [%4];" \
        : "=r"(r0), "=r"(r1), "=r"(r2), "=r"(r3) : "r"(addr))

#define MMA_BF16(c, a, b0, b1) \
    asm volatile("mma.sync.aligned.m16n8k16.row.col.f32.bf16.bf16.f32 " \
        "{%0,%1,%2,%3},{%4,%5,%6,%7},{%8,%9},{%0,%1,%2,%3};" \
        : "+f"((c)[0]), "+f"((c)[1]), "+f"((c)[2]), "+f"((c)[3]) \
        : "r"((a)[0]), "r"((a)[1]), "r"((a)[2]), "r"((a)[3]), "r"(b0), "r"(b1))

__device__ __forceinline__ uint32_t pack_bf16x2(__nv_bfloat16 a, __nv_bfloat16 b) {
    __nv_bfloat162 p;
    p.x = a; p.y = b;
    return *reinterpret_cast<uint32_t*>(&p);
}
// split two f32 into (hi, lo) bf16x2 words
__device__ __forceinline__ void split2(float x0, float x1, uint32_t& hw, uint32_t& lw) {
    __nv_bfloat16 h0 = __float2bfloat16(x0);
    __nv_bfloat16 h1 = __float2bfloat16(x1);
    __nv_bfloat16 l0 = __float2bfloat16(x0 - __bfloat162float(h0));
    __nv_bfloat16 l1 = __float2bfloat16(x1 - __bfloat162float(h1));
    hw = pack_bf16x2(h0, h1);
    lw = pack_bf16x2(l0, l1);
}

// Scratch (device globals; no allocation allowed)
__device__ float g_q[ROWS * DK];
__device__ float g_kv[ROWS * DK];
__device__ float g_att[ROWS * DK];

// ---------------------------------------------------------------------------
// Kernel 1: shared input projection via split-bf16 tensor-core MMA.
//   dst = src @ Wi + bi,  src 32768x512 (q rows then kv rows), Wi 512x64.
// CTA: 128 rows x 64 cols, 256 threads = 8 warps of 32x32 tiles.
// k-chunks of 32; per k16: ldmatrix fragments + 24 HMMA (3-term split).
// smem stride = 40 bf16 (80B) -> ldmatrix 8-row phases conflict-free.
// ---------------------------------------------------------------------------
#define ASTRIDE 40   // bf16 units per row (32 data + 8 pad)

__global__ void __launch_bounds__(256) proj_kernel(const float* __restrict__ query,
                                                   const float* __restrict__ value,
                                                   const float* __restrict__ Wi,
                                                   const float* __restrict__ bi)
{
    __shared__ __align__(16) __nv_bfloat16 Ah[128 * ASTRIDE];
    __shared__ __align__(16) __nv_bfloat16 Al[128 * ASTRIDE];
    __shared__ __align__(16) __nv_bfloat16 Wh[64 * ASTRIDE];
    __shared__ __align__(16) __nv_bfloat16 Wl[64 * ASTRIDE];

    const int t    = threadIdx.x;
    const int lane = t & 31;
    const int warp = t >> 5;
    const int row0 = blockIdx.x * 128;

    const float* src;
    float* dst;
    int roff;
    if (row0 < ROWS) { src = query; dst = g_q;  roff = row0; }
    else             { src = value; dst = g_kv; roff = row0 - ROWS; }

    const int wm = warp & 3;          // 4 slabs of 32 rows
    const int wn = warp >> 2;         // 2 slabs of 32 cols
    const int m_base = wm * 32;
    const int n_base = wn * 32;

    // loader indices
    const int lr = t >> 1;            // A loader row 0..127
    const int lh = (t & 1) * 16;      // A loader k-half
    const int wcol = t & 63;          // W loader col
    const int wkg  = t >> 6;          // W loader k-group (8 k each)

    // ldmatrix lane addressing
    const int a_row = lane & 15;
    const int a_c8  = (lane >> 4) * 8;
    const int b_row = (lane & 7) + ((lane >> 4) & 1) * 8;
    const int b_c8  = ((lane >> 3) & 1) * 8;

    const uint32_t ahB = (uint32_t)__cvta_generic_to_shared(Ah);
    const uint32_t alB = (uint32_t)__cvta_generic_to_shared(Al);
    const uint32_t whB = (uint32_t)__cvta_generic_to_shared(Wh);
    const uint32_t wlB = (uint32_t)__cvta_generic_to_shared(Wl);

    uint32_t* ahW = reinterpret_cast<uint32_t*>(Ah);
    uint32_t* alW = reinterpret_cast<uint32_t*>(Al);
    uint32_t* whW = reinterpret_cast<uint32_t*>(Wh);
    uint32_t* wlW = reinterpret_cast<uint32_t*>(Wl);

    float c[2][4][4];
#pragma unroll
    for (int m = 0; m < 2; m++)
#pragma unroll
        for (int n = 0; n < 4; n++)
#pragma unroll
            for (int r = 0; r < 4; r++) c[m][n][r] = 0.0f;

    for (int k0 = 0; k0 < DIM; k0 += 32) {
        __syncthreads();
        // ---- load & split A chunk: 128 rows x 32 k ----
        {
            const float4* ap = reinterpret_cast<const float4*>(
                src + (size_t)(roff + lr) * DIM + k0 + lh);
            float4 f0 = ap[0], f1 = ap[1], f2 = ap[2], f3 = ap[3];
            uint32_t hw[8], lw[8];
            split2(f0.x, f0.y, hw[0], lw[0]);
            split2(f0.z, f0.w, hw[1], lw[1]);
            split2(f1.x, f1.y, hw[2], lw[2]);
            split2(f1.z, f1.w, hw[3], lw[3]);
            split2(f2.x, f2.y, hw[4], lw[4]);
            split2(f2.z, f2.w, hw[5], lw[5]);
            split2(f3.x, f3.y, hw[6], lw[6]);
            split2(f3.z, f3.w, hw[7], lw[7]);
            int wo = lr * (ASTRIDE / 2) + (lh >> 1);
            *reinterpret_cast<uint4*>(ahW + wo)     = make_uint4(hw[0], hw[1], hw[2], hw[3]);
            *reinterpret_cast<uint4*>(ahW + wo + 4) = make_uint4(hw[4], hw[5], hw[6], hw[7]);
            *reinterpret_cast<uint4*>(alW + wo)     = make_uint4(lw[0], lw[1], lw[2], lw[3]);
            *reinterpret_cast<uint4*>(alW + wo + 4) = make_uint4(lw[4], lw[5], lw[6], lw[7]);
        }
        // ---- load & split W chunk: 32 k x 64 n, stored [n][k] ----
        {
            const float* wp = Wi + (size_t)(k0 + wkg * 8) * DK + wcol;
            float wv[8];
#pragma unroll
            for (int j = 0; j < 8; j++) wv[j] = wp[j * DK];
            uint32_t hw[4], lw[4];
            split2(wv[0], wv[1], hw[0], lw[0]);
            split2(wv[2], wv[3], hw[1], lw[1]);
            split2(wv[4], wv[5], hw[2], lw[2]);
            split2(wv[6], wv[7], hw[3], lw[3]);
            int wo = wcol * (ASTRIDE / 2) + wkg * 4;
            *reinterpret_cast<uint4*>(whW + wo) = make_uint4(hw[0], hw[1], hw[2], hw[3]);
            *reinterpret_cast<uint4*>(wlW + wo) = make_uint4(lw[0], lw[1], lw[2], lw[3]);
        }
        __syncthreads();

#pragma unroll
        for (int ks = 0; ks < 32; ks += 16) {
            // A fragments (hi & lo) for two m16 tiles
            uint32_t ah0[4], ah1[4], al0[4], al1[4];
            {
                uint32_t off0 = (uint32_t)(((m_base + a_row) * ASTRIDE + ks + a_c8) * 2);
                uint32_t off1 = off0 + 16 * ASTRIDE * 2;
                LDSM_X4(ah0[0], ah0[1], ah0[2], ah0[3], ahB + off0);
                LDSM_X4(ah1[0], ah1[1], ah1[2], ah1[3], ahB + off1);
                LDSM_X4(al0[0], al0[1], al0[2], al0[3], alB + off0);
                LDSM_X4(al1[0], al1[1], al1[2], al1[3], alB + off1);
            }
            // B fragments: 4 n8 blocks (hi & lo)
            uint32_t bh[8], bl[8];
            {
                uint32_t off0 = (uint32_t)(((n_base + b_row) * ASTRIDE + ks + b_c8) * 2);
                uint32_t off1 = off0 + 16 * ASTRIDE * 2;
                LDSM_X4(bh[0], bh[1], bh[2], bh[3], whB + off0);
                LDSM_X4(bh[4], bh[5], bh[6], bh[7], whB + off1);
                LDSM_X4(bl[0], bl[1], bl[2], bl[3], wlB + off0);
                LDSM_X4(bl[4], bl[5], bl[6], bl[7], wlB + off1);
            }
#pragma unroll
            for (int n = 0; n < 4; n++) {
                MMA_BF16(c[0][n], ah0, bh[2 * n], bh[2 * n + 1]);
                MMA_BF16(c[0][n], ah0, bl[2 * n], bl[2 * n + 1]);
                MMA_BF16(c[0][n], al0, bh[2 * n], bh[2 * n + 1]);
                MMA_BF16(c[1][n], ah1, bh[2 * n], bh[2 * n + 1]);
                MMA_BF16(c[1][n], ah1, bl[2 * n], bl[2 * n + 1]);
                MMA_BF16(c[1][n], al1, bh[2 * n], bh[2 * n + 1]);
            }
        }
    }

    // epilogue: add bias, store
    const int g = lane >> 2, tig = lane & 3;
#pragma unroll
    for (int m = 0; m < 2; m++) {
        int row = roff + m_base + m * 16 + g;
#pragma unroll
        for (int n = 0; n < 4; n++) {
            int col = n_base + n * 8 + tig * 2;
            float b0v = bi[col], b1v = bi[col + 1];
            float2 o0 = {c[m][n][0] + b0v, c[m][n][1] + b1v};
            float2 o1 = {c[m][n][2] + b0v, c[m][n][3] + b1v};
            *reinterpret_cast<float2*>(&dst[(size_t)row * DK + col]) = o0;
            *reinterpret_cast<float2*>(&dst[(size_t)(row + 8) * DK + col]) = o1;
        }
    }
}

// ---------------------------------------------------------------------------
// Kernel 2: banded attention (f32x2 scalar path, unchanged from R6).
//   att[i,:] = sum_{|i-j|<=128} (q_i . kv_j) * SCALE * kv_j
// ---------------------------------------------------------------------------
#define ATTN_SMEM_FLOATS (4*64*68)

__global__ void __launch_bounds__(128) attn_kernel()
{
    extern __shared__ __align__(16) float sm[];
    float (*qT)[68]  = reinterpret_cast<float(*)[68]>(sm);
    float (*kvT)[68] = reinterpret_cast<float(*)[68]>(sm + 64 * 68);
    float (*kvR)[68] = reinterpret_cast<float(*)[68]>(sm + 2 * 64 * 68);
    float (*Ssm)[68] = reinterpret_cast<float(*)[68]>(sm + 3 * 64 * 68);

    const int t  = threadIdx.x;
    const int b  = blockIdx.x >> 6;
    const int qs = blockIdx.x & 63;
    const int q0 = qs * 64;

    const int lr = t >> 1;
    const int lh = (t & 1) * 32;

    const float* qg = g_q + ((size_t)b * SEQ + q0) * DK;
#pragma unroll
    for (int v = 0; v < 8; v++) {
        float4 x = reinterpret_cast<const float4*>(qg + (size_t)lr * DK + lh)[v];
        int k = lh + v * 4;
        qT[k + 0][lr] = x.x;
        qT[k + 1][lr] = x.y;
        qT[k + 2][lr] = x.z;
        qT[k + 3][lr] = x.w;
    }

    const int arow = t >> 4, acol = t & 15;
    const int brow = t >> 3, bcol = t & 7;
    const int i0a = arow * 8, j0a = acol * 4;
    const int i0b = brow * 4, d0 = bcol * 8;

    ull bacc[4][4];
#pragma unroll
    for (int r = 0; r < 4; r++)
#pragma unroll
        for (int c = 0; c < 4; c++) bacc[r][c] = 0ull;

    for (int jt = qs - 2; jt <= qs + 2; jt++) {
        if (jt < 0 || jt >= 64) continue;
        __syncthreads();

        const float* kg = g_kv + ((size_t)b * SEQ + jt * 64) * DK;
#pragma unroll
        for (int v = 0; v < 8; v++) {
            float4 x = reinterpret_cast<const float4*>(kg + (size_t)lr * DK + lh)[v];
            int k = lh + v * 4;
            kvT[k + 0][lr] = x.x;
            kvT[k + 1][lr] = x.y;
            kvT[k + 2][lr] = x.z;
            kvT[k + 3][lr] = x.w;
            reinterpret_cast<float4*>(&kvR[lr][lh])[v] = x;
        }
        __syncthreads();

        ull sacc[8][2];
#pragma unroll
        for (int r = 0; r < 8; r++) { sacc[r][0] = 0ull; sacc[r][1] = 0ull; }

#pragma unroll 8
        for (int k = 0; k < DK; k++) {
            float4 a0 = *reinterpret_cast<const float4*>(&qT[k][i0a]);
            float4 a1 = *reinterpret_cast<const float4*>(&qT[k][i0a + 4]);
            ull pa[8];
            pa[0] = bcast2(a0.x); pa[1] = bcast2(a0.y);
            pa[2] = bcast2(a0.z); pa[3] = bcast2(a0.w);
            pa[4] = bcast2(a1.x); pa[5] = bcast2(a1.y);
            pa[6] = bcast2(a1.z); pa[7] = bcast2(a1.w);
            ulonglong2 bb = *reinterpret_cast<const ulonglong2*>(&kvT[k][j0a]);
#pragma unroll
            for (int r = 0; r < 8; r++) {
                sacc[r][0] = ffma2(pa[r], bb.x, sacc[r][0]);
                sacc[r][1] = ffma2(pa[r], bb.y, sacc[r][1]);
            }
        }

        const int jbase = jt * 64;
#pragma unroll
        for (int r = 0; r < 8; r++) {
            int gi = q0 + i0a + r;
            float v[4];
            unpack2(sacc[r][0], v[0], v[1]);
            unpack2(sacc[r][1], v[2], v[3]);
            float4 o;
            {
                int gj = jbase + j0a;
                int d0m = gi - gj;
                o.x = (d0m <= BAND && d0m >= -BAND) ? v[0] * SCALE : 0.0f;
                int d1m = d0m - 1;
                o.y = (d1m <= BAND && d1m >= -BAND) ? v[1] * SCALE : 0.0f;
                int d2m = d0m - 2;
                o.z = (d2m <= BAND && d2m >= -BAND) ? v[2] * SCALE : 0.0f;
                int d3m = d0m - 3;
                o.w = (d3m <= BAND && d3m >= -BAND) ? v[3] * SCALE : 0.0f;
            }
            *reinterpret_cast<float4*>(&Ssm[i0a + r][j0a]) = o;
        }
        __syncthreads();

#pragma unroll 4
        for (int j = 0; j < 64; j++) {
            ull ps[4];
            ps[0] = bcast2(Ssm[i0b + 0][j]);
            ps[1] = bcast2(Ssm[i0b + 1][j]);
            ps[2] = bcast2(Ssm[i0b + 2][j]);
            ps[3] = bcast2(Ssm[i0b + 3][j]);
            ulonglong2 v0 = *reinterpret_cast<const ulonglong2*>(&kvR[j][d0]);
            ulonglong2 v1 = *reinterpret_cast<const ulonglong2*>(&kvR[j][d0 + 4]);
#pragma unroll
            for (int r = 0; r < 4; r++) {
                bacc[r][0] = ffma2(ps[r], v0.x, bacc[r][0]);
                bacc[r][1] = ffma2(ps[r], v0.y, bacc[r][1]);
                bacc[r][2] = ffma2(ps[r], v1.x, bacc[r][2]);
                bacc[r][3] = ffma2(ps[r], v1.y, bacc[r][3]);
            }
        }
    }

    float* og = g_att + ((size_t)b * SEQ + q0) * DK;
#pragma unroll
    for (int r = 0; r < 4; r++) {
        float v[8];
        unpack2(bacc[r][0], v[0], v[1]);
        unpack2(bacc[r][1], v[2], v[3]);
        unpack2(bacc[r][2], v[4], v[5]);
        unpack2(bacc[r][3], v[6], v[7]);
        float4 o0 = {v[0], v[1], v[2], v[3]};
        float4 o1 = {v[4], v[5], v[6], v[7]};
        float* p = og + (size_t)(i0b + r) * DK + d0;
        reinterpret_cast<float4*>(p)[0] = o0;
        reinterpret_cast<float4*>(p)[1] = o1;
    }
}

// ---------------------------------------------------------------------------
// Kernel 3: out = att @ Wo + bo    [16384,64]x[64,512]  (unchanged from R6)
// ---------------------------------------------------------------------------
#define OUT_SMEM_FLOATS (64*132 + 64*128)

__global__ void __launch_bounds__(256) out_kernel(const float* __restrict__ Wo,
                                                  const float* __restrict__ bo,
                                                  float* __restrict__ out)
{
    extern __shared__ __align__(16) float smo[];
    float (*attT)[132] = reinterpret_cast<float(*)[132]>(smo);
    float (*WoS)[128]  = reinterpret_cast<float(*)[128]>(smo + 64 * 132);

    const int t    = threadIdx.x;
    const int rb   = blockIdx.x >> 2;
    const int cb   = blockIdx.x & 3;
    const int row0 = rb * 128;
    const int col0 = cb * 128;

    {
        int lrow = t >> 1;
        int lh   = (t & 1) * 32;
        const float* ap = g_att + (size_t)(row0 + lrow) * DK + lh;
#pragma unroll
        for (int v = 0; v < 8; v++) {
            float4 x = reinterpret_cast<const float4*>(ap)[v];
            int kk = lh + v * 4;
            attT[kk + 0][lrow] = x.x;
            attT[kk + 1][lrow] = x.y;
            attT[kk + 2][lrow] = x.z;
            attT[kk + 3][lrow] = x.w;
        }
    }
    {
#pragma unroll
        for (int v = 0; v < 8; v++) {
            int f = v * 256 + t;
            int wk = f >> 5;
            int wc = (f & 31) * 4;
            *reinterpret_cast<float4*>(&WoS[wk][wc]) =
                *reinterpret_cast<const float4*>(Wo + (size_t)wk * DIM + col0 + wc);
        }
    }
    __syncthreads();

    const int trow = t >> 4;
    const int tcol = t & 15;
    const int r0 = trow * 8, c0 = tcol * 8;

    ull acc[8][4];
#pragma unroll
    for (int r = 0; r < 8; r++)
#pragma unroll
        for (int c = 0; c < 4; c++) acc[r][c] = 0ull;

#pragma unroll 8
    for (int k = 0; k < DK; k++) {
        float4 a0 = *reinterpret_cast<const float4*>(&attT[k][r0]);
        float4 a1 = *reinterpret_cast<const float4*>(&attT[k][r0 + 4]);
        ull pa[8];
        pa[0] = bcast2(a0.x); pa[1] = bcast2(a0.y);
        pa[2] = bcast2(a0.z); pa[3] = bcast2(a0.w);
        pa[4] = bcast2(a1.x); pa[5] = bcast2(a1.y);
        pa[6] = bcast2(a1.z); pa[7] = bcast2(a1.w);
        ulonglong2 b0 = *reinterpret_cast<const ulonglong2*>(&WoS[k][c0]);
        ulonglong2 b1 = *reinterpret_cast<const ulonglong2*>(&WoS[k][c0 + 4]);
#pragma unroll
        for (int r = 0; r < 8; r++) {
            acc[r][0] = ffma2(pa[r], b0.x, acc[r][0]);
            acc[r][1] = ffma2(pa[r], b0.y, acc[r][1]);
            acc[r][2] = ffma2(pa[r], b1.x, acc[r][2]);
            acc[r][3] = ffma2(pa[r], b1.y, acc[r][3]);
        }
    }

    float bb[8];
#pragma unroll
    for (int c = 0; c < 8; c++) bb[c] = bo[col0 + c0 + c];

#pragma unroll
    for (int r = 0; r < 8; r++) {
        float v[8];
        unpack2(acc[r][0], v[0], v[1]);
        unpack2(acc[r][1], v[2], v[3]);
        unpack2(acc[r][2], v[4], v[5]);
        unpack2(acc[r][3], v[6], v[7]);
        float4 o0 = {v[0] + bb[0], v[1] + bb[1], v[2] + bb[2], v[3] + bb[3]};
        float4 o1 = {v[4] + bb[4], v[5] + bb[5], v[6] + bb[6], v[7] + bb[7]};
        float* p = out + (size_t)(row0 + r0 + r) * DIM + col0 + c0;
        reinterpret_cast<float4*>(p)[0] = o0;
        reinterpret_cast<float4*>(p)[1] = o1;
    }
}

// ---------------------------------------------------------------------------
extern "C" void kernel_launch(void* const* d_in, const int* in_sizes, int n_in,
                              void* d_out, int out_size)
{
    const float* query = (const float*)d_in[0];
    const float* value = (const float*)d_in[1];
    const float* Wi    = (const float*)d_in[2];
    const float* bi    = (const float*)d_in[3];
    const float* Wo    = (const float*)d_in[4];
    const float* bo    = (const float*)d_in[5];
    float* out = (float*)d_out;

    static bool attr_set = false;
    if (!attr_set) {
        cudaFuncSetAttribute(attn_kernel, cudaFuncAttributeMaxDynamicSharedMemorySize,
                             ATTN_SMEM_FLOATS * (int)sizeof(float));
        cudaFuncSetAttribute(out_kernel, cudaFuncAttributeMaxDynamicSharedMemorySize,
                             OUT_SMEM_FLOATS * (int)sizeof(float));
        attr_set = true;
    }

    proj_kernel<<<MTOT / 128, 256>>>(query, value, Wi, bi);
    attn_kernel<<<BATCH * (SEQ / 64), 128, ATTN_SMEM_FLOATS * (int)sizeof(float)>>>();
    out_kernel<<<(ROWS / 128) * (DIM / 128), 256, OUT_SMEM_FLOATS * (int)sizeof(float)>>>(Wo, bo, out);
}

// round 8
// speedup vs baseline: 1.8154x; 1.1100x over previous
#include <cuda_runtime.h>
#include <cuda_bf16.h>
#include <cstdint>

// Problem constants (fixed by dataset)
#define BATCH 4
#define SEQ   4096
#define DIM   512
#define DK    64
#define BAND  128
#define SCALE 0.125f            // 1/sqrt(64)
#define ROWS  (BATCH*SEQ)       // 16384
#define MTOT  (2*ROWS)          // 32768 (q rows then kv rows)

// ---- tensor-core helpers ---------------------------------------------------
#define LDSM_X4(r0, r1, r2, r3, addr) \
    asm volatile("ldmatrix.sync.aligned.m8n8.x4.shared.b16 {%0,%1,%2,%3}, [%4];" \
        : "=r"(r0), "=r"(r1), "=r"(r2), "=r"(r3) : "r"(addr))

#define LDSM_X4_T(r0, r1, r2, r3, addr) \
    asm volatile("ldmatrix.sync.aligned.m8n8.x4.trans.shared.b16 {%0,%1,%2,%3}, [%4];" \
        : "=r"(r0), "=r"(r1), "=r"(r2), "=r"(r3) : "r"(addr))

#define MMA_BF16(c, a, b0, b1) \
    asm volatile("mma.sync.aligned.m16n8k16.row.col.f32.bf16.bf16.f32 " \
        "{%0,%1,%2,%3},{%4,%5,%6,%7},{%8,%9},{%0,%1,%2,%3};" \
        : "+f"((c)[0]), "+f"((c)[1]), "+f"((c)[2]), "+f"((c)[3]) \
        : "r"((a)[0]), "r"((a)[1]), "r"((a)[2]), "r"((a)[3]), "r"(b0), "r"(b1))

__device__ __forceinline__ uint32_t pack_bf16x2(__nv_bfloat16 a, __nv_bfloat16 b) {
    __nv_bfloat162 p;
    p.x = a; p.y = b;
    return *reinterpret_cast<uint32_t*>(&p);
}
// split two f32 into (hi, lo) bf16x2 words
__device__ __forceinline__ void split2(float x0, float x1, uint32_t& hw, uint32_t& lw) {
    __nv_bfloat16 h0 = __float2bfloat16(x0);
    __nv_bfloat16 h1 = __float2bfloat16(x1);
    __nv_bfloat16 l0 = __float2bfloat16(x0 - __bfloat162float(h0));
    __nv_bfloat16 l1 = __float2bfloat16(x1 - __bfloat162float(h1));
    hw = pack_bf16x2(h0, h1);
    lw = pack_bf16x2(l0, l1);
}

// Scratch (device globals; no allocation allowed). All split bf16 hi/lo pairs.
__device__ __nv_bfloat16 g_qh[ROWS * DK];
__device__ __nv_bfloat16 g_ql[ROWS * DK];
__device__ __nv_bfloat16 g_kvh[ROWS * DK];
__device__ __nv_bfloat16 g_kvl[ROWS * DK];
__device__ __nv_bfloat16 g_atth[ROWS * DK];
__device__ __nv_bfloat16 g_attl[ROWS * DK];

// ---------------------------------------------------------------------------
// Kernel 1: shared input projection via split-bf16 tensor-core MMA.
//   dst(split) = src @ Wi + bi,  src 32768x512, Wi 512x64.
// CTA: 128 rows x 64 cols, 256 threads = 8 warps of 32x32 tiles.
// ---------------------------------------------------------------------------
#define ASTRIDE 40   // bf16 units per row (32 data + 8 pad)

__global__ void __launch_bounds__(256) proj_kernel(const float* __restrict__ query,
                                                   const float* __restrict__ value,
                                                   const float* __restrict__ Wi,
                                                   const float* __restrict__ bi)
{
    __shared__ __align__(16) __nv_bfloat16 Ah[128 * ASTRIDE];
    __shared__ __align__(16) __nv_bfloat16 Al[128 * ASTRIDE];
    __shared__ __align__(16) __nv_bfloat16 Wh[64 * ASTRIDE];
    __shared__ __align__(16) __nv_bfloat16 Wl[64 * ASTRIDE];

    const int t    = threadIdx.x;
    const int lane = t & 31;
    const int warp = t >> 5;
    const int row0 = blockIdx.x * 128;

    const float* src;
    uint32_t* dsth;
    uint32_t* dstl;
    int roff;
    if (row0 < ROWS) {
        src = query;
        dsth = reinterpret_cast<uint32_t*>(g_qh);
        dstl = reinterpret_cast<uint32_t*>(g_ql);
        roff = row0;
    } else {
        src = value;
        dsth = reinterpret_cast<uint32_t*>(g_kvh);
        dstl = reinterpret_cast<uint32_t*>(g_kvl);
        roff = row0 - ROWS;
    }

    const int wm = warp & 3;
    const int wn = warp >> 2;
    const int m_base = wm * 32;
    const int n_base = wn * 32;

    const int lr = t >> 1;
    const int lh = (t & 1) * 16;
    const int wcol = t & 63;
    const int wkg  = t >> 6;

    const int a_row = lane & 15;
    const int a_c8  = (lane >> 4) * 8;
    const int b_row = (lane & 7) + ((lane >> 4) & 1) * 8;
    const int b_c8  = ((lane >> 3) & 1) * 8;

    const uint32_t ahB = (uint32_t)__cvta_generic_to_shared(Ah);
    const uint32_t alB = (uint32_t)__cvta_generic_to_shared(Al);
    const uint32_t whB = (uint32_t)__cvta_generic_to_shared(Wh);
    const uint32_t wlB = (uint32_t)__cvta_generic_to_shared(Wl);

    uint32_t* ahW = reinterpret_cast<uint32_t*>(Ah);
    uint32_t* alW = reinterpret_cast<uint32_t*>(Al);
    uint32_t* whW = reinterpret_cast<uint32_t*>(Wh);
    uint32_t* wlW = reinterpret_cast<uint32_t*>(Wl);

    float c[2][4][4];
#pragma unroll
    for (int m = 0; m < 2; m++)
#pragma unroll
        for (int n = 0; n < 4; n++)
#pragma unroll
            for (int r = 0; r < 4; r++) c[m][n][r] = 0.0f;

    for (int k0 = 0; k0 < DIM; k0 += 32) {
        __syncthreads();
        {
            const float4* ap = reinterpret_cast<const float4*>(
                src + (size_t)(roff + lr) * DIM + k0 + lh);
            float4 f0 = ap[0], f1 = ap[1], f2 = ap[2], f3 = ap[3];
            uint32_t hw[8], lw[8];
            split2(f0.x, f0.y, hw[0], lw[0]);
            split2(f0.z, f0.w, hw[1], lw[1]);
            split2(f1.x, f1.y, hw[2], lw[2]);
            split2(f1.z, f1.w, hw[3], lw[3]);
            split2(f2.x, f2.y, hw[4], lw[4]);
            split2(f2.z, f2.w, hw[5], lw[5]);
            split2(f3.x, f3.y, hw[6], lw[6]);
            split2(f3.z, f3.w, hw[7], lw[7]);
            int wo = lr * (ASTRIDE / 2) + (lh >> 1);
            *reinterpret_cast<uint4*>(ahW + wo)     = make_uint4(hw[0], hw[1], hw[2], hw[3]);
            *reinterpret_cast<uint4*>(ahW + wo + 4) = make_uint4(hw[4], hw[5], hw[6], hw[7]);
            *reinterpret_cast<uint4*>(alW + wo)     = make_uint4(lw[0], lw[1], lw[2], lw[3]);
            *reinterpret_cast<uint4*>(alW + wo + 4) = make_uint4(lw[4], lw[5], lw[6], lw[7]);
        }
        {
            const float* wp = Wi + (size_t)(k0 + wkg * 8) * DK + wcol;
            float wv[8];
#pragma unroll
            for (int j = 0; j < 8; j++) wv[j] = wp[j * DK];
            uint32_t hw[4], lw[4];
            split2(wv[0], wv[1], hw[0], lw[0]);
            split2(wv[2], wv[3], hw[1], lw[1]);
            split2(wv[4], wv[5], hw[2], lw[2]);
            split2(wv[6], wv[7], hw[3], lw[3]);
            int wo = wcol * (ASTRIDE / 2) + wkg * 4;
            *reinterpret_cast<uint4*>(whW + wo) = make_uint4(hw[0], hw[1], hw[2], hw[3]);
            *reinterpret_cast<uint4*>(wlW + wo) = make_uint4(lw[0], lw[1], lw[2], lw[3]);
        }
        __syncthreads();

#pragma unroll
        for (int ks = 0; ks < 32; ks += 16) {
            uint32_t ah0[4], ah1[4], al0[4], al1[4];
            {
                uint32_t off0 = (uint32_t)(((m_base + a_row) * ASTRIDE + ks + a_c8) * 2);
                uint32_t off1 = off0 + 16 * ASTRIDE * 2;
                LDSM_X4(ah0[0], ah0[1], ah0[2], ah0[3], ahB + off0);
                LDSM_X4(ah1[0], ah1[1], ah1[2], ah1[3], ahB + off1);
                LDSM_X4(al0[0], al0[1], al0[2], al0[3], alB + off0);
                LDSM_X4(al1[0], al1[1], al1[2], al1[3], alB + off1);
            }
            uint32_t bh[8], bl[8];
            {
                uint32_t off0 = (uint32_t)(((n_base + b_row) * ASTRIDE + ks + b_c8) * 2);
                uint32_t off1 = off0 + 16 * ASTRIDE * 2;
                LDSM_X4(bh[0], bh[1], bh[2], bh[3], whB + off0);
                LDSM_X4(bh[4], bh[5], bh[6], bh[7], whB + off1);
                LDSM_X4(bl[0], bl[1], bl[2], bl[3], wlB + off0);
                LDSM_X4(bl[4], bl[5], bl[6], bl[7], wlB + off1);
            }
#pragma unroll
            for (int n = 0; n < 4; n++) {
                MMA_BF16(c[0][n], ah0, bh[2 * n], bh[2 * n + 1]);
                MMA_BF16(c[0][n], ah0, bl[2 * n], bl[2 * n + 1]);
                MMA_BF16(c[0][n], al0, bh[2 * n], bh[2 * n + 1]);
                MMA_BF16(c[1][n], ah1, bh[2 * n], bh[2 * n + 1]);
                MMA_BF16(c[1][n], ah1, bl[2 * n], bl[2 * n + 1]);
                MMA_BF16(c[1][n], al1, bh[2 * n], bh[2 * n + 1]);
            }
        }
    }

    // epilogue: add bias, split to bf16 hi/lo, store packed words
    const int g = lane >> 2, tig = lane & 3;
#pragma unroll
    for (int m = 0; m < 2; m++) {
        int row = roff + m_base + m * 16 + g;
#pragma unroll
        for (int n = 0; n < 4; n++) {
            int col = n_base + n * 8 + tig * 2;
            float b0v = bi[col], b1v = bi[col + 1];
            uint32_t hw, lw;
            split2(c[m][n][0] + b0v, c[m][n][1] + b1v, hw, lw);
            dsth[(size_t)row * 32 + (col >> 1)] = hw;
            dstl[(size_t)row * 32 + (col >> 1)] = lw;
            split2(c[m][n][2] + b0v, c[m][n][3] + b1v, hw, lw);
            dsth[(size_t)(row + 8) * 32 + (col >> 1)] = hw;
            dstl[(size_t)(row + 8) * 32 + (col >> 1)] = lw;
        }
    }
}

// ---------------------------------------------------------------------------
// Kernel 2: banded attention, fully on tensor cores (flash-style).
//   att[i,:] = sum_{|i-j|<=128} (q_i . kv_j) * SCALE * kv_j
// CTA = (batch, 64-row q tile), 128 threads = 4 warps (16 rows each).
// Phase A: S = Q @ K^T via MMA (K smem [j][dk] is B-operand layout directly).
// Phase B: att += S @ KV; S a-frags come from phase-A C-frags (register reuse),
//          KV b-frags via ldmatrix.trans on the same K tiles.
// ---------------------------------------------------------------------------
#define QSTR 72   // bf16 stride for 64-wide tiles (144B rows, conflict-free)

__global__ void __launch_bounds__(128) attn_kernel()
{
    __shared__ __align__(16) __nv_bfloat16 Qh[64 * QSTR];
    __shared__ __align__(16) __nv_bfloat16 Ql[64 * QSTR];
    __shared__ __align__(16) __nv_bfloat16 Kh[64 * QSTR];
    __shared__ __align__(16) __nv_bfloat16 Kl[64 * QSTR];

    const int t    = threadIdx.x;
    const int lane = t & 31;
    const int warp = t >> 5;
    const int b    = blockIdx.x >> 6;
    const int qs   = blockIdx.x & 63;
    const int q0   = qs * 64;
    const int m_base = warp * 16;

    const uint32_t qhB = (uint32_t)__cvta_generic_to_shared(Qh);
    const uint32_t qlB = (uint32_t)__cvta_generic_to_shared(Ql);
    const uint32_t khB = (uint32_t)__cvta_generic_to_shared(Kh);
    const uint32_t klB = (uint32_t)__cvta_generic_to_shared(Kl);

    // loaders: 64 rows x 64 bf16, each thread one half-row (32 bf16 = 4x uint4)
    const int lr = t >> 1;
    const int lhf = t & 1;

    {
        size_t gbase = ((size_t)b * SEQ + q0 + lr) * DK;
        const uint4* sh = reinterpret_cast<const uint4*>(g_qh + gbase) + lhf * 4;
        const uint4* sl = reinterpret_cast<const uint4*>(g_ql + gbase) + lhf * 4;
        uint4* dh = reinterpret_cast<uint4*>(&Qh[lr * QSTR + lhf * 32]);
        uint4* dl = reinterpret_cast<uint4*>(&Ql[lr * QSTR + lhf * 32]);
#pragma unroll
        for (int v = 0; v < 4; v++) { dh[v] = sh[v]; dl[v] = sl[v]; }
    }
    __syncthreads();

    // ldmatrix lane addressing
    const int a_row = lane & 15;
    const int a_c8  = (lane >> 4) * 8;                       // A-operand (non-trans)
    const int b_row = (lane & 7) + ((lane >> 4) & 1) * 8;    // B-operand (non-trans)
    const int b_c8  = ((lane >> 3) & 1) * 8;
    const int tj    = (lane & 7) + ((lane >> 3) & 1) * 8;    // B-operand (trans)
    const int td8   = (lane >> 4) * 8;

    // Q a-fragments: persistent across all j-tiles
    uint32_t qha[4][4], qla[4][4];
#pragma unroll
    for (int kc = 0; kc < 4; kc++) {
        uint32_t off = (uint32_t)(((m_base + a_row) * QSTR + kc * 16 + a_c8) * 2);
        LDSM_X4(qha[kc][0], qha[kc][1], qha[kc][2], qha[kc][3], qhB + off);
        LDSM_X4(qla[kc][0], qla[kc][1], qla[kc][2], qla[kc][3], qlB + off);
    }

    float attv[8][4];
#pragma unroll
    for (int n = 0; n < 8; n++)
#pragma unroll
        for (int r = 0; r < 4; r++) attv[n][r] = 0.0f;

    const int g = lane >> 2, tq = lane & 3;

    for (int jt = qs - 2; jt <= qs + 2; jt++) {
        if (jt < 0 || jt >= 64) continue;
        __syncthreads();
        // load K tile (split bf16) into smem
        {
            size_t gbase = ((size_t)b * SEQ + jt * 64 + lr) * DK;
            const uint4* sh = reinterpret_cast<const uint4*>(g_kvh + gbase) + lhf * 4;
            const uint4* sl = reinterpret_cast<const uint4*>(g_kvl + gbase) + lhf * 4;
            uint4* dh = reinterpret_cast<uint4*>(&Kh[lr * QSTR + lhf * 32]);
            uint4* dl = reinterpret_cast<uint4*>(&Kl[lr * QSTR + lhf * 32]);
#pragma unroll
            for (int v = 0; v < 4; v++) { dh[v] = sh[v]; dl[v] = sl[v]; }
        }
        __syncthreads();

        // ---- Phase A: S (m16 x n64) = Q K^T, 3-term split ----
        float S[8][4];
#pragma unroll
        for (int n = 0; n < 8; n++)
#pragma unroll
            for (int r = 0; r < 4; r++) S[n][r] = 0.0f;

#pragma unroll
        for (int kc = 0; kc < 4; kc++) {
#pragma unroll
            for (int ng = 0; ng < 4; ng++) {
                uint32_t off = (uint32_t)(((ng * 16 + b_row) * QSTR + kc * 16 + b_c8) * 2);
                uint32_t bh[4], bl[4];
                LDSM_X4(bh[0], bh[1], bh[2], bh[3], khB + off);
                LDSM_X4(bl[0], bl[1], bl[2], bl[3], klB + off);
                MMA_BF16(S[2 * ng],     qha[kc], bh[0], bh[1]);
                MMA_BF16(S[2 * ng],     qha[kc], bl[0], bl[1]);
                MMA_BF16(S[2 * ng],     qla[kc], bh[0], bh[1]);
                MMA_BF16(S[2 * ng + 1], qha[kc], bh[2], bh[3]);
                MMA_BF16(S[2 * ng + 1], qha[kc], bl[2], bl[3]);
                MMA_BF16(S[2 * ng + 1], qla[kc], bh[2], bh[3]);
            }
        }

        // ---- mask + scale in registers ----
        const int jbase = jt * 64;
        const int gi0 = q0 + m_base + g;
#pragma unroll
        for (int n = 0; n < 8; n++) {
            int gj = jbase + n * 8 + tq * 2;
            int d0 = gi0 - gj;          // row g, col 2t
            int d1 = d0 - 1;            // row g, col 2t+1
            int d2 = d0 + 8;            // row g+8, col 2t
            int d3 = d2 - 1;
            S[n][0] = (d0 <= BAND && d0 >= -BAND) ? S[n][0] * SCALE : 0.0f;
            S[n][1] = (d1 <= BAND && d1 >= -BAND) ? S[n][1] * SCALE : 0.0f;
            S[n][2] = (d2 <= BAND && d2 >= -BAND) ? S[n][2] * SCALE : 0.0f;
            S[n][3] = (d3 <= BAND && d3 >= -BAND) ? S[n][3] * SCALE : 0.0f;
        }

        // ---- split S C-frags into phase-B A-frags (register reuse) ----
        uint32_t pah[4][4], pal[4][4];
#pragma unroll
        for (int kc = 0; kc < 4; kc++) {
            split2(S[2 * kc][0],     S[2 * kc][1],     pah[kc][0], pal[kc][0]);
            split2(S[2 * kc][2],     S[2 * kc][3],     pah[kc][1], pal[kc][1]);
            split2(S[2 * kc + 1][0], S[2 * kc + 1][1], pah[kc][2], pal[kc][2]);
            split2(S[2 * kc + 1][2], S[2 * kc + 1][3], pah[kc][3], pal[kc][3]);
        }

        // ---- Phase B: att += S @ KV, B-frags via ldmatrix.trans ----
#pragma unroll
        for (int kc = 0; kc < 4; kc++) {
#pragma unroll
            for (int dg = 0; dg < 4; dg++) {
                uint32_t off = (uint32_t)(((kc * 16 + tj) * QSTR + dg * 16 + td8) * 2);
                uint32_t vh[4], vl[4];
                LDSM_X4_T(vh[0], vh[1], vh[2], vh[3], khB + off);
                LDSM_X4_T(vl[0], vl[1], vl[2], vl[3], klB + off);
                MMA_BF16(attv[2 * dg],     pah[kc], vh[0], vh[1]);
                MMA_BF16(attv[2 * dg],     pah[kc], vl[0], vl[1]);
                MMA_BF16(attv[2 * dg],     pal[kc], vh[0], vh[1]);
                MMA_BF16(attv[2 * dg + 1], pah[kc], vh[2], vh[3]);
                MMA_BF16(attv[2 * dg + 1], pah[kc], vl[2], vl[3]);
                MMA_BF16(attv[2 * dg + 1], pal[kc], vh[2], vh[3]);
            }
        }
    }

    // epilogue: split att accumulators to bf16 hi/lo, store packed words
    uint32_t* atth_w = reinterpret_cast<uint32_t*>(g_atth);
    uint32_t* attl_w = reinterpret_cast<uint32_t*>(g_attl);
    const size_t rbase = (size_t)b * SEQ + q0 + m_base + g;
#pragma unroll
    for (int n = 0; n < 8; n++) {
        int cw = n * 4 + tq;   // word index = col/2
        uint32_t hw, lw;
        split2(attv[n][0], attv[n][1], hw, lw);
        atth_w[rbase * 32 + cw] = hw;
        attl_w[rbase * 32 + cw] = lw;
        split2(attv[n][2], attv[n][3], hw, lw);
        atth_w[(rbase + 8) * 32 + cw] = hw;
        attl_w[(rbase + 8) * 32 + cw] = lw;
    }
}

// ---------------------------------------------------------------------------
// Kernel 3: out = att @ Wo + bo via split-bf16 MMA.  [16384,64]x[64,512]
// CTA: 128 rows x 128 cols, 256 threads = 8 warps (wm 0..3 x wn 0..1).
// A = att (pre-split bf16), B = Wo split in-kernel, kept [k][n], ldmatrix.trans.
// ---------------------------------------------------------------------------
#define WSTR 136   // bf16 stride for 128-wide Wo tiles (272B rows, conflict-free)
#define OUT_SMEM_BYTES ((2*128*QSTR + 2*64*WSTR) * 2)

__global__ void __launch_bounds__(256) out_kernel(const float* __restrict__ Wo,
                                                  const float* __restrict__ bo,
                                                  float* __restrict__ out)
{
    extern __shared__ __align__(16) __nv_bfloat16 smo[];
    __nv_bfloat16* Ah = smo;
    __nv_bfloat16* Al = Ah + 128 * QSTR;
    __nv_bfloat16* Wh = Al + 128 * QSTR;
    __nv_bfloat16* Wl = Wh + 64 * WSTR;

    const int t    = threadIdx.x;
    const int lane = t & 31;
    const int warp = t >> 5;
    const int rb   = blockIdx.x >> 2;
    const int cb   = blockIdx.x & 3;
    const int row0 = rb * 128;
    const int col0 = cb * 128;

    const int wm = warp & 3;     // 32-row slab (2 m16)
    const int wn = warp >> 2;    // 64-col slab (8 n8)

    const uint32_t ahB = (uint32_t)__cvta_generic_to_shared(Ah);
    const uint32_t alB = (uint32_t)__cvta_generic_to_shared(Al);
    const uint32_t whB = (uint32_t)__cvta_generic_to_shared(Wh);
    const uint32_t wlB = (uint32_t)__cvta_generic_to_shared(Wl);

    // load att tile (split bf16): 128 rows, each thread one half-row
    {
        int lr = t >> 1, lhf = t & 1;
        size_t gbase = (size_t)(row0 + lr) * DK;
        const uint4* sh = reinterpret_cast<const uint4*>(g_atth + gbase) + lhf * 4;
        const uint4* sl = reinterpret_cast<const uint4*>(g_attl + gbase) + lhf * 4;
        uint4* dh = reinterpret_cast<uint4*>(&Ah[lr * QSTR + lhf * 32]);
        uint4* dl = reinterpret_cast<uint4*>(&Al[lr * QSTR + lhf * 32]);
#pragma unroll
        for (int v = 0; v < 4; v++) { dh[v] = sh[v]; dl[v] = sl[v]; }
    }
    // load + split Wo tile: [64 k][128 n], keep [k][n]
    {
        int wk = t >> 2, seg = (t & 3) * 32;
        const float4* wp = reinterpret_cast<const float4*>(Wo + (size_t)wk * DIM + col0 + seg);
        uint32_t* whW = reinterpret_cast<uint32_t*>(&Wh[wk * WSTR + seg]);
        uint32_t* wlW = reinterpret_cast<uint32_t*>(&Wl[wk * WSTR + seg]);
#pragma unroll
        for (int v = 0; v < 8; v += 2) {
            float4 f0 = wp[v], f1 = wp[v + 1];
            uint32_t hw[4], lw[4];
            split2(f0.x, f0.y, hw[0], lw[0]);
            split2(f0.z, f0.w, hw[1], lw[1]);
            split2(f1.x, f1.y, hw[2], lw[2]);
            split2(f1.z, f1.w, hw[3], lw[3]);
            *reinterpret_cast<uint4*>(whW + v * 2) = make_uint4(hw[0], hw[1], hw[2], hw[3]);
            *reinterpret_cast<uint4*>(wlW + v * 2) = make_uint4(lw[0], lw[1], lw[2], lw[3]);
        }
    }
    __syncthreads();

    const int a_row = lane & 15;
    const int a_c8  = (lane >> 4) * 8;
    const int tj    = (lane & 7) + ((lane >> 3) & 1) * 8;
    const int td8   = (lane >> 4) * 8;

    float c[2][8][4];
#pragma unroll
    for (int m = 0; m < 2; m++)
#pragma unroll
        for (int n = 0; n < 8; n++)
#pragma unroll
            for (int r = 0; r < 4; r++) c[m][n][r] = 0.0f;

#pragma unroll
    for (int kc = 0; kc < 4; kc++) {
        uint32_t ah[2][4], al[2][4];
#pragma unroll
        for (int m = 0; m < 2; m++) {
            uint32_t off = (uint32_t)(((wm * 32 + m * 16 + a_row) * QSTR + kc * 16 + a_c8) * 2);
            LDSM_X4(ah[m][0], ah[m][1], ah[m][2], ah[m][3], ahB + off);
            LDSM_X4(al[m][0], al[m][1], al[m][2], al[m][3], alB + off);
        }
#pragma unroll
        for (int dg = 0; dg < 4; dg++) {
            uint32_t off = (uint32_t)(((kc * 16 + tj) * WSTR + wn * 64 + dg * 16 + td8) * 2);
            uint32_t vh[4], vl[4];
            LDSM_X4_T(vh[0], vh[1], vh[2], vh[3], whB + off);
            LDSM_X4_T(vl[0], vl[1], vl[2], vl[3], wlB + off);
#pragma unroll
            for (int m = 0; m < 2; m++) {
                MMA_BF16(c[m][2 * dg],     ah[m], vh[0], vh[1]);
                MMA_BF16(c[m][2 * dg],     ah[m], vl[0], vl[1]);
                MMA_BF16(c[m][2 * dg],     al[m], vh[0], vh[1]);
                MMA_BF16(c[m][2 * dg + 1], ah[m], vh[2], vh[3]);
                MMA_BF16(c[m][2 * dg + 1], ah[m], vl[2], vl[3]);
                MMA_BF16(c[m][2 * dg + 1], al[m], vh[2], vh[3]);
            }
        }
    }

    // epilogue: bias + fp32 store
    const int g = lane >> 2, tq = lane & 3;
#pragma unroll
    for (int m = 0; m < 2; m++) {
        int row = row0 + wm * 32 + m * 16 + g;
#pragma unroll
        for (int n = 0; n < 8; n++) {
            int col = col0 + wn * 64 + n * 8 + tq * 2;
            float b0v = bo[col], b1v = bo[col + 1];
            float2 o0 = {c[m][n][0] + b0v, c[m][n][1] + b1v};
            float2 o1 = {c[m][n][2] + b0v, c[m][n][3] + b1v};
            *reinterpret_cast<float2*>(&out[(size_t)row * DIM + col]) = o0;
            *reinterpret_cast<float2*>(&out[(size_t)(row + 8) * DIM + col]) = o1;
        }
    }
}

// ---------------------------------------------------------------------------
extern "C" void kernel_launch(void* const* d_in, const int* in_sizes, int n_in,
                              void* d_out, int out_size)
{
    const float* query = (const float*)d_in[0];
    const float* value = (const float*)d_in[1];
    const float* Wi    = (const float*)d_in[2];
    const float* bi    = (const float*)d_in[3];
    const float* Wo    = (const float*)d_in[4];
    const float* bo    = (const float*)d_in[5];
    float* out = (float*)d_out;

    static bool attr_set = false;
    if (!attr_set) {
        cudaFuncSetAttribute(out_kernel, cudaFuncAttributeMaxDynamicSharedMemorySize,
                             OUT_SMEM_BYTES);
        attr_set = true;
    }

    proj_kernel<<<MTOT / 128, 256>>>(query, value, Wi, bi);
    attn_kernel<<<BATCH * (SEQ / 64), 128>>>();
    out_kernel<<<(ROWS / 128) * (DIM / 128), 256, OUT_SMEM_BYTES>>>(Wo, bo, out);
}

// round 9
// speedup vs baseline: 2.5674x; 1.4142x over previous
#include <cuda_runtime.h>
#include <cuda_bf16.h>
#include <cstdint>

// Problem constants (fixed by dataset)
#define BATCH 4
#define SEQ   4096
#define DIM   512
#define DK    64
#define BAND  128
#define SCALE 0.125f            // 1/sqrt(64)
#define ROWS  (BATCH*SEQ)       // 16384
#define MTOT  (2*ROWS)          // 32768 (q rows then kv rows)

// ---- tensor-core helpers ---------------------------------------------------
#define LDSM_X4(r0, r1, r2, r3, addr) \
    asm volatile("ldmatrix.sync.aligned.m8n8.x4.shared.b16 {%0,%1,%2,%3}, [%4];" \
        : "=r"(r0), "=r"(r1), "=r"(r2), "=r"(r3) : "r"(addr))

#define LDSM_X4_T(r0, r1, r2, r3, addr) \
    asm volatile("ldmatrix.sync.aligned.m8n8.x4.trans.shared.b16 {%0,%1,%2,%3}, [%4];" \
        : "=r"(r0), "=r"(r1), "=r"(r2), "=r"(r3) : "r"(addr))

#define MMA_BF16(c, a, b0, b1) \
    asm volatile("mma.sync.aligned.m16n8k16.row.col.f32.bf16.bf16.f32 " \
        "{%0,%1,%2,%3},{%4,%5,%6,%7},{%8,%9},{%0,%1,%2,%3};" \
        : "+f"((c)[0]), "+f"((c)[1]), "+f"((c)[2]), "+f"((c)[3]) \
        : "r"((a)[0]), "r"((a)[1]), "r"((a)[2]), "r"((a)[3]), "r"(b0), "r"(b1))

__device__ __forceinline__ uint32_t pack_bf16x2(__nv_bfloat16 a, __nv_bfloat16 b) {
    __nv_bfloat162 p;
    p.x = a; p.y = b;
    return *reinterpret_cast<uint32_t*>(&p);
}
// split two f32 into (hi, lo) bf16x2 words
__device__ __forceinline__ void split2(float x0, float x1, uint32_t& hw, uint32_t& lw) {
    __nv_bfloat16 h0 = __float2bfloat16(x0);
    __nv_bfloat16 h1 = __float2bfloat16(x1);
    __nv_bfloat16 l0 = __float2bfloat16(x0 - __bfloat162float(h0));
    __nv_bfloat16 l1 = __float2bfloat16(x1 - __bfloat162float(h1));
    hw = pack_bf16x2(h0, h1);
    lw = pack_bf16x2(l0, l1);
}

// Scratch (device globals; no allocation allowed). All split bf16 hi/lo pairs.
__device__ __nv_bfloat16 g_qh[ROWS * DK];
__device__ __nv_bfloat16 g_ql[ROWS * DK];
__device__ __nv_bfloat16 g_kvh[ROWS * DK];
__device__ __nv_bfloat16 g_kvl[ROWS * DK];
__device__ __nv_bfloat16 g_atth[ROWS * DK];
__device__ __nv_bfloat16 g_attl[ROWS * DK];

// ---------------------------------------------------------------------------
// Kernel 1: shared input projection via split-bf16 tensor-core MMA.
//   dst(split) = src @ Wi + bi,  src 32768x512, Wi 512x64.
// CTA: 64 rows x 64 cols, 256 threads = 8 warps (wm 0..3 m16, wn 0..1 n32).
// Double-buffered smem + register prefetch of the next k-chunk.
// ---------------------------------------------------------------------------
#define ASTRIDE 40   // bf16 units per row (32 data + 8 pad)

__global__ void __launch_bounds__(256) proj_kernel(const float* __restrict__ query,
                                                   const float* __restrict__ value,
                                                   const float* __restrict__ Wi,
                                                   const float* __restrict__ bi)
{
    __shared__ __align__(16) __nv_bfloat16 Ah[2][64 * ASTRIDE];
    __shared__ __align__(16) __nv_bfloat16 Al[2][64 * ASTRIDE];
    __shared__ __align__(16) __nv_bfloat16 Wh[2][64 * ASTRIDE];  // [n][k]
    __shared__ __align__(16) __nv_bfloat16 Wl[2][64 * ASTRIDE];

    const int t    = threadIdx.x;
    const int lane = t & 31;
    const int warp = t >> 5;
    const int row0 = blockIdx.x * 64;

    const float* src;
    uint32_t* dsth;
    uint32_t* dstl;
    int roff;
    if (row0 < ROWS) {
        src = query;
        dsth = reinterpret_cast<uint32_t*>(g_qh);
        dstl = reinterpret_cast<uint32_t*>(g_ql);
        roff = row0;
    } else {
        src = value;
        dsth = reinterpret_cast<uint32_t*>(g_kvh);
        dstl = reinterpret_cast<uint32_t*>(g_kvl);
        roff = row0 - ROWS;
    }

    const int wm = warp & 3;
    const int wn = warp >> 2;
    const int m_base = wm * 16;
    const int n_base = wn * 32;

    // A loader: 64 rows x 32 k, each thread 8 fp32 (2 float4) of one row
    const int lr = t >> 2;
    const int ls = (t & 3) * 8;
    // W loader: col wcol, k-group wkg (8 k each)
    const int wcol = t & 63;
    const int wkg  = t >> 6;

    // ldmatrix lane addressing
    const int a_row = lane & 15;
    const int a_c8  = (lane >> 4) * 8;
    const int b_row = (lane & 7) + ((lane >> 4) & 1) * 8;
    const int b_c8  = ((lane >> 3) & 1) * 8;

    const uint32_t ahB0 = (uint32_t)__cvta_generic_to_shared(Ah);
    const uint32_t alB0 = (uint32_t)__cvta_generic_to_shared(Al);
    const uint32_t whB0 = (uint32_t)__cvta_generic_to_shared(Wh);
    const uint32_t wlB0 = (uint32_t)__cvta_generic_to_shared(Wl);
    const uint32_t bufBytes = 64 * ASTRIDE * 2;

    float c[4][4];
#pragma unroll
    for (int n = 0; n < 4; n++)
#pragma unroll
        for (int r = 0; r < 4; r++) c[n][r] = 0.0f;

    // prefetch registers
    float4 fA0, fA1;
    float wv[8];

    // load chunk 0
    {
        const float4* ap = reinterpret_cast<const float4*>(src + (size_t)(roff + lr) * DIM + ls);
        fA0 = ap[0]; fA1 = ap[1];
        const float* wp = Wi + (size_t)(wkg * 8) * DK + wcol;
#pragma unroll
        for (int j = 0; j < 8; j++) wv[j] = wp[j * DK];
    }

    for (int k0i = 0; k0i < 16; k0i++) {
        const int buf = k0i & 1;
        // split + store prefetched chunk into smem[buf]
        {
            uint32_t hw[4], lw[4];
            split2(fA0.x, fA0.y, hw[0], lw[0]);
            split2(fA0.z, fA0.w, hw[1], lw[1]);
            split2(fA1.x, fA1.y, hw[2], lw[2]);
            split2(fA1.z, fA1.w, hw[3], lw[3]);
            int wo = lr * (ASTRIDE / 2) + (ls >> 1);
            *reinterpret_cast<uint4*>(reinterpret_cast<uint32_t*>(Ah[buf]) + wo) =
                make_uint4(hw[0], hw[1], hw[2], hw[3]);
            *reinterpret_cast<uint4*>(reinterpret_cast<uint32_t*>(Al[buf]) + wo) =
                make_uint4(lw[0], lw[1], lw[2], lw[3]);
            split2(wv[0], wv[1], hw[0], lw[0]);
            split2(wv[2], wv[3], hw[1], lw[1]);
            split2(wv[4], wv[5], hw[2], lw[2]);
            split2(wv[6], wv[7], hw[3], lw[3]);
            int wo2 = wcol * (ASTRIDE / 2) + wkg * 4;
            *reinterpret_cast<uint4*>(reinterpret_cast<uint32_t*>(Wh[buf]) + wo2) =
                make_uint4(hw[0], hw[1], hw[2], hw[3]);
            *reinterpret_cast<uint4*>(reinterpret_cast<uint32_t*>(Wl[buf]) + wo2) =
                make_uint4(lw[0], lw[1], lw[2], lw[3]);
        }
        __syncthreads();

        // issue global loads for next chunk (overlap with MMA below)
        if (k0i < 15) {
            int k0 = (k0i + 1) * 32;
            const float4* ap = reinterpret_cast<const float4*>(
                src + (size_t)(roff + lr) * DIM + k0 + ls);
            fA0 = ap[0]; fA1 = ap[1];
            const float* wp = Wi + (size_t)(k0 + wkg * 8) * DK + wcol;
#pragma unroll
            for (int j = 0; j < 8; j++) wv[j] = wp[j * DK];
        }

        const uint32_t ahB = ahB0 + buf * bufBytes;
        const uint32_t alB = alB0 + buf * bufBytes;
        const uint32_t whB = whB0 + buf * bufBytes;
        const uint32_t wlB = wlB0 + buf * bufBytes;

#pragma unroll
        for (int ks = 0; ks < 32; ks += 16) {
            uint32_t ah[4], al[4];
            {
                uint32_t off = (uint32_t)(((m_base + a_row) * ASTRIDE + ks + a_c8) * 2);
                LDSM_X4(ah[0], ah[1], ah[2], ah[3], ahB + off);
                LDSM_X4(al[0], al[1], al[2], al[3], alB + off);
            }
            uint32_t bh[8], bl[8];
            {
                uint32_t off0 = (uint32_t)(((n_base + b_row) * ASTRIDE + ks + b_c8) * 2);
                uint32_t off1 = off0 + 16 * ASTRIDE * 2;
                LDSM_X4(bh[0], bh[1], bh[2], bh[3], whB + off0);
                LDSM_X4(bh[4], bh[5], bh[6], bh[7], whB + off1);
                LDSM_X4(bl[0], bl[1], bl[2], bl[3], wlB + off0);
                LDSM_X4(bl[4], bl[5], bl[6], bl[7], wlB + off1);
            }
#pragma unroll
            for (int n = 0; n < 4; n++) {
                MMA_BF16(c[n], ah, bh[2 * n], bh[2 * n + 1]);
                MMA_BF16(c[n], ah, bl[2 * n], bl[2 * n + 1]);
                MMA_BF16(c[n], al, bh[2 * n], bh[2 * n + 1]);
            }
        }
    }

    // epilogue: add bias, split to bf16 hi/lo, store packed words
    const int g = lane >> 2, tig = lane & 3;
    {
        int row = roff + m_base + g;
#pragma unroll
        for (int n = 0; n < 4; n++) {
            int col = n_base + n * 8 + tig * 2;
            float b0v = bi[col], b1v = bi[col + 1];
            uint32_t hw, lw;
            split2(c[n][0] + b0v, c[n][1] + b1v, hw, lw);
            dsth[(size_t)row * 32 + (col >> 1)] = hw;
            dstl[(size_t)row * 32 + (col >> 1)] = lw;
            split2(c[n][2] + b0v, c[n][3] + b1v, hw, lw);
            dsth[(size_t)(row + 8) * 32 + (col >> 1)] = hw;
            dstl[(size_t)(row + 8) * 32 + (col >> 1)] = lw;
        }
    }
}

// ---------------------------------------------------------------------------
// Kernel 2: banded attention, tensor cores, j-split across 8 warps.
//   att[i,:] = sum_{|i-j|<=128} (q_i . kv_j) * SCALE * kv_j
// CTA = (batch, 64-row q tile), 256 threads: warp = (wm 0..3, wj 0..1).
// Each warp: m16 rows x 32-j half. attv partials in regs across 5 tiles;
// one smem reduction at the end. Exact block-skip for out-of-band blocks.
// ---------------------------------------------------------------------------
#define QSTR 72   // bf16 stride for 64-wide tiles (144B rows)

__global__ void __launch_bounds__(256) attn_kernel()
{
    __shared__ __align__(16) __nv_bfloat16 Qh[64 * QSTR];
    __shared__ __align__(16) __nv_bfloat16 Ql[64 * QSTR];
    __shared__ __align__(16) __nv_bfloat16 Kh[64 * QSTR];
    __shared__ __align__(16) __nv_bfloat16 Kl[64 * QSTR];
    __shared__ __align__(16) float red[64][66];

    const int t    = threadIdx.x;
    const int lane = t & 31;
    const int warp = t >> 5;
    const int b    = blockIdx.x >> 6;
    const int qs   = blockIdx.x & 63;
    const int q0   = qs * 64;

    const int wm = warp & 3;
    const int wj = warp >> 2;
    const int m_base = wm * 16;
    const int jcol0  = wj * 32;

    const uint32_t qhB = (uint32_t)__cvta_generic_to_shared(Qh);
    const uint32_t qlB = (uint32_t)__cvta_generic_to_shared(Ql);
    const uint32_t khB = (uint32_t)__cvta_generic_to_shared(Kh);
    const uint32_t klB = (uint32_t)__cvta_generic_to_shared(Kl);

    // load Q tile (split bf16): 512 uint4 per array, 2 per thread
#pragma unroll
    for (int f = t; f < 512; f += 256) {
        int r = f >> 3, s = f & 7;
        size_t gb = ((size_t)b * SEQ + q0 + r) * DK;
        reinterpret_cast<uint4*>(&Qh[r * QSTR])[s] =
            reinterpret_cast<const uint4*>(g_qh + gb)[s];
        reinterpret_cast<uint4*>(&Ql[r * QSTR])[s] =
            reinterpret_cast<const uint4*>(g_ql + gb)[s];
    }
    __syncthreads();

    // ldmatrix lane addressing
    const int a_row = lane & 15;
    const int a_c8  = (lane >> 4) * 8;
    const int b_row = (lane & 7) + ((lane >> 4) & 1) * 8;
    const int b_c8  = ((lane >> 3) & 1) * 8;
    const int tj    = (lane & 7) + ((lane >> 3) & 1) * 8;
    const int td8   = (lane >> 4) * 8;

    // Q a-fragments: persistent across all j-tiles
    uint32_t qha[4][4], qla[4][4];
#pragma unroll
    for (int kc = 0; kc < 4; kc++) {
        uint32_t off = (uint32_t)(((m_base + a_row) * QSTR + kc * 16 + a_c8) * 2);
        LDSM_X4(qha[kc][0], qha[kc][1], qha[kc][2], qha[kc][3], qhB + off);
        LDSM_X4(qla[kc][0], qla[kc][1], qla[kc][2], qla[kc][3], qlB + off);
    }

    float attv[8][4];
#pragma unroll
    for (int n = 0; n < 8; n++)
#pragma unroll
        for (int r = 0; r < 4; r++) attv[n][r] = 0.0f;

    const int g = lane >> 2, tq = lane & 3;
    const int gi_lo = q0 + m_base;
    const int gi_hi = gi_lo + 15;

    for (int jt = qs - 2; jt <= qs + 2; jt++) {
        if (jt < 0 || jt >= 64) continue;
        __syncthreads();   // previous tile's reads done before overwrite
        // load K tile (split bf16)
#pragma unroll
        for (int f = t; f < 512; f += 256) {
            int r = f >> 3, s = f & 7;
            size_t gb = ((size_t)b * SEQ + jt * 64 + r) * DK;
            reinterpret_cast<uint4*>(&Kh[r * QSTR])[s] =
                reinterpret_cast<const uint4*>(g_kvh + gb)[s];
            reinterpret_cast<uint4*>(&Kl[r * QSTR])[s] =
                reinterpret_cast<const uint4*>(g_kvl + gb)[s];
        }
        __syncthreads();

        const int jbase = jt * 64;

        // block in-band predicates for the two 16-wide j blocks of this warp
        bool keep[2];
#pragma unroll
        for (int blk = 0; blk < 2; blk++) {
            int jlo = jbase + jcol0 + blk * 16;
            keep[blk] = !(gi_lo - (jlo + 15) > BAND || jlo - gi_hi > BAND);
        }

        // ---- Phase A: S (m16 x n32) = Q K^T, 3-term split ----
        float S[4][4];
#pragma unroll
        for (int n = 0; n < 4; n++)
#pragma unroll
            for (int r = 0; r < 4; r++) S[n][r] = 0.0f;

#pragma unroll
        for (int kc = 0; kc < 4; kc++) {
#pragma unroll
            for (int ng = 0; ng < 2; ng++) {
                if (!keep[ng]) continue;
                uint32_t off = (uint32_t)(((jcol0 + ng * 16 + b_row) * QSTR + kc * 16 + b_c8) * 2);
                uint32_t bh[4], bl[4];
                LDSM_X4(bh[0], bh[1], bh[2], bh[3], khB + off);
                LDSM_X4(bl[0], bl[1], bl[2], bl[3], klB + off);
                MMA_BF16(S[2 * ng],     qha[kc], bh[0], bh[1]);
                MMA_BF16(S[2 * ng],     qha[kc], bl[0], bl[1]);
                MMA_BF16(S[2 * ng],     qla[kc], bh[0], bh[1]);
                MMA_BF16(S[2 * ng + 1], qha[kc], bh[2], bh[3]);
                MMA_BF16(S[2 * ng + 1], qha[kc], bl[2], bl[3]);
                MMA_BF16(S[2 * ng + 1], qla[kc], bh[2], bh[3]);
            }
        }

        // ---- mask + scale in registers ----
        const int gi0 = gi_lo + g;
#pragma unroll
        for (int n = 0; n < 4; n++) {
            int gj = jbase + jcol0 + n * 8 + tq * 2;
            int d0 = gi0 - gj;
            int d1 = d0 - 1;
            int d2 = d0 + 8;
            int d3 = d2 - 1;
            S[n][0] = (d0 <= BAND && d0 >= -BAND) ? S[n][0] * SCALE : 0.0f;
            S[n][1] = (d1 <= BAND && d1 >= -BAND) ? S[n][1] * SCALE : 0.0f;
            S[n][2] = (d2 <= BAND && d2 >= -BAND) ? S[n][2] * SCALE : 0.0f;
            S[n][3] = (d3 <= BAND && d3 >= -BAND) ? S[n][3] * SCALE : 0.0f;
        }

        // ---- split S C-frags into phase-B A-frags ----
        uint32_t pah[2][4], pal[2][4];
#pragma unroll
        for (int kc = 0; kc < 2; kc++) {
            split2(S[2 * kc][0],     S[2 * kc][1],     pah[kc][0], pal[kc][0]);
            split2(S[2 * kc][2],     S[2 * kc][3],     pah[kc][1], pal[kc][1]);
            split2(S[2 * kc + 1][0], S[2 * kc + 1][1], pah[kc][2], pal[kc][2]);
            split2(S[2 * kc + 1][2], S[2 * kc + 1][3], pah[kc][3], pal[kc][3]);
        }

        // ---- Phase B: attv += S @ KV (this warp's j-half) ----
#pragma unroll
        for (int kc = 0; kc < 2; kc++) {
            if (!keep[kc]) continue;
#pragma unroll
            for (int dg = 0; dg < 4; dg++) {
                uint32_t off = (uint32_t)(((jcol0 + kc * 16 + tj) * QSTR + dg * 16 + td8) * 2);
                uint32_t vh[4], vl[4];
                LDSM_X4_T(vh[0], vh[1], vh[2], vh[3], khB + off);
                LDSM_X4_T(vl[0], vl[1], vl[2], vl[3], klB + off);
                MMA_BF16(attv[2 * dg],     pah[kc], vh[0], vh[1]);
                MMA_BF16(attv[2 * dg],     pah[kc], vl[0], vl[1]);
                MMA_BF16(attv[2 * dg],     pal[kc], vh[0], vh[1]);
                MMA_BF16(attv[2 * dg + 1], pah[kc], vh[2], vh[3]);
                MMA_BF16(attv[2 * dg + 1], pah[kc], vl[2], vl[3]);
                MMA_BF16(attv[2 * dg + 1], pal[kc], vh[2], vh[3]);
            }
        }
    }

    // ---- cross-warp reduction over wj, then epilogue ----
    __syncthreads();
    if (wj == 1) {
#pragma unroll
        for (int n = 0; n < 8; n++) {
            int col = n * 8 + tq * 2;
            *reinterpret_cast<float2*>(&red[m_base + g][col])     = make_float2(attv[n][0], attv[n][1]);
            *reinterpret_cast<float2*>(&red[m_base + g + 8][col]) = make_float2(attv[n][2], attv[n][3]);
        }
    }
    __syncthreads();
    if (wj == 0) {
        uint32_t* atth_w = reinterpret_cast<uint32_t*>(g_atth);
        uint32_t* attl_w = reinterpret_cast<uint32_t*>(g_attl);
        const size_t rbase = (size_t)b * SEQ + q0 + m_base + g;
#pragma unroll
        for (int n = 0; n < 8; n++) {
            int col = n * 8 + tq * 2;
            float2 r0 = *reinterpret_cast<const float2*>(&red[m_base + g][col]);
            float2 r1 = *reinterpret_cast<const float2*>(&red[m_base + g + 8][col]);
            int cw = n * 4 + tq;
            uint32_t hw, lw;
            split2(attv[n][0] + r0.x, attv[n][1] + r0.y, hw, lw);
            atth_w[rbase * 32 + cw] = hw;
            attl_w[rbase * 32 + cw] = lw;
            split2(attv[n][2] + r1.x, attv[n][3] + r1.y, hw, lw);
            atth_w[(rbase + 8) * 32 + cw] = hw;
            attl_w[(rbase + 8) * 32 + cw] = lw;
        }
    }
}

// ---------------------------------------------------------------------------
// Kernel 3: out = att @ Wo + bo via split-bf16 MMA.  [16384,64]x[64,512]
// CTA: 128 rows x 128 cols, 256 threads = 8 warps (wm 0..3 x wn 0..1).
// ---------------------------------------------------------------------------
#define WSTR 136   // bf16 stride for 128-wide Wo tiles
#define OUT_SMEM_BYTES ((2*128*QSTR + 2*64*WSTR) * 2)

__global__ void __launch_bounds__(256) out_kernel(const float* __restrict__ Wo,
                                                  const float* __restrict__ bo,
                                                  float* __restrict__ out)
{
    extern __shared__ __align__(16) __nv_bfloat16 smo[];
    __nv_bfloat16* Ah = smo;
    __nv_bfloat16* Al = Ah + 128 * QSTR;
    __nv_bfloat16* Wh = Al + 128 * QSTR;
    __nv_bfloat16* Wl = Wh + 64 * WSTR;

    const int t    = threadIdx.x;
    const int lane = t & 31;
    const int warp = t >> 5;
    const int rb   = blockIdx.x >> 2;
    const int cb   = blockIdx.x & 3;
    const int row0 = rb * 128;
    const int col0 = cb * 128;

    const int wm = warp & 3;
    const int wn = warp >> 2;

    const uint32_t ahB = (uint32_t)__cvta_generic_to_shared(Ah);
    const uint32_t alB = (uint32_t)__cvta_generic_to_shared(Al);
    const uint32_t whB = (uint32_t)__cvta_generic_to_shared(Wh);
    const uint32_t wlB = (uint32_t)__cvta_generic_to_shared(Wl);

    // load att tile (split bf16): 128 rows, each thread one half-row
    {
        int lr = t >> 1, lhf = t & 1;
        size_t gbase = (size_t)(row0 + lr) * DK;
        const uint4* sh = reinterpret_cast<const uint4*>(g_atth + gbase) + lhf * 4;
        const uint4* sl = reinterpret_cast<const uint4*>(g_attl + gbase) + lhf * 4;
        uint4* dh = reinterpret_cast<uint4*>(&Ah[lr * QSTR + lhf * 32]);
        uint4* dl = reinterpret_cast<uint4*>(&Al[lr * QSTR + lhf * 32]);
#pragma unroll
        for (int v = 0; v < 4; v++) { dh[v] = sh[v]; dl[v] = sl[v]; }
    }
    // load + split Wo tile: [64 k][128 n], keep [k][n]
    {
        int wk = t >> 2, seg = (t & 3) * 32;
        const float4* wp = reinterpret_cast<const float4*>(Wo + (size_t)wk * DIM + col0 + seg);
        uint32_t* whW = reinterpret_cast<uint32_t*>(&Wh[wk * WSTR + seg]);
        uint32_t* wlW = reinterpret_cast<uint32_t*>(&Wl[wk * WSTR + seg]);
#pragma unroll
        for (int v = 0; v < 8; v += 2) {
            float4 f0 = wp[v], f1 = wp[v + 1];
            uint32_t hw[4], lw[4];
            split2(f0.x, f0.y, hw[0], lw[0]);
            split2(f0.z, f0.w, hw[1], lw[1]);
            split2(f1.x, f1.y, hw[2], lw[2]);
            split2(f1.z, f1.w, hw[3], lw[3]);
            *reinterpret_cast<uint4*>(whW + v * 2) = make_uint4(hw[0], hw[1], hw[2], hw[3]);
            *reinterpret_cast<uint4*>(wlW + v * 2) = make_uint4(lw[0], lw[1], lw[2], lw[3]);
        }
    }
    __syncthreads();

    const int a_row = lane & 15;
    const int a_c8  = (lane >> 4) * 8;
    const int tj    = (lane & 7) + ((lane >> 3) & 1) * 8;
    const int td8   = (lane >> 4) * 8;

    float c[2][8][4];
#pragma unroll
    for (int m = 0; m < 2; m++)
#pragma unroll
        for (int n = 0; n < 8; n++)
#pragma unroll
            for (int r = 0; r < 4; r++) c[m][n][r] = 0.0f;

#pragma unroll
    for (int kc = 0; kc < 4; kc++) {
        uint32_t ah[2][4], al[2][4];
#pragma unroll
        for (int m = 0; m < 2; m++) {
            uint32_t off = (uint32_t)(((wm * 32 + m * 16 + a_row) * QSTR + kc * 16 + a_c8) * 2);
            LDSM_X4(ah[m][0], ah[m][1], ah[m][2], ah[m][3], ahB + off);
            LDSM_X4(al[m][0], al[m][1], al[m][2], al[m][3], alB + off);
        }
#pragma unroll
        for (int dg = 0; dg < 4; dg++) {
            uint32_t off = (uint32_t)(((kc * 16 + tj) * WSTR + wn * 64 + dg * 16 + td8) * 2);
            uint32_t vh[4], vl[4];
            LDSM_X4_T(vh[0], vh[1], vh[2], vh[3], whB + off);
            LDSM_X4_T(vl[0], vl[1], vl[2], vl[3], wlB + off);
#pragma unroll
            for (int m = 0; m < 2; m++) {
                MMA_BF16(c[m][2 * dg],     ah[m], vh[0], vh[1]);
                MMA_BF16(c[m][2 * dg],     ah[m], vl[0], vl[1]);
                MMA_BF16(c[m][2 * dg],     al[m], vh[0], vh[1]);
                MMA_BF16(c[m][2 * dg + 1], ah[m], vh[2], vh[3]);
                MMA_BF16(c[m][2 * dg + 1], ah[m], vl[2], vl[3]);
                MMA_BF16(c[m][2 * dg + 1], al[m], vh[2], vh[3]);
            }
        }
    }

    // epilogue: bias + fp32 store
    const int g = lane >> 2, tq = lane & 3;
#pragma unroll
    for (int m = 0; m < 2; m++) {
        int row = row0 + wm * 32 + m * 16 + g;
#pragma unroll
        for (int n = 0; n < 8; n++) {
            int col = col0 + wn * 64 + n * 8 + tq * 2;
            float b0v = bo[col], b1v = bo[col + 1];
            float2 o0 = {c[m][n][0] + b0v, c[m][n][1] + b1v};
            float2 o1 = {c[m][n][2] + b0v, c[m][n][3] + b1v};
            *reinterpret_cast<float2*>(&out[(size_t)row * DIM + col]) = o0;
            *reinterpret_cast<float2*>(&out[(size_t)(row + 8) * DIM + col]) = o1;
        }
    }
}

// ---------------------------------------------------------------------------
extern "C" void kernel_launch(void* const* d_in, const int* in_sizes, int n_in,
                              void* d_out, int out_size)
{
    const float* query = (const float*)d_in[0];
    const float* value = (const float*)d_in[1];
    const float* Wi    = (const float*)d_in[2];
    const float* bi    = (const float*)d_in[3];
    const float* Wo    = (const float*)d_in[4];
    const float* bo    = (const float*)d_in[5];
    float* out = (float*)d_out;

    static bool attr_set = false;
    if (!attr_set) {
        cudaFuncSetAttribute(out_kernel, cudaFuncAttributeMaxDynamicSharedMemorySize,
                             OUT_SMEM_BYTES);
        attr_set = true;
    }

    proj_kernel<<<MTOT / 64, 256>>>(query, value, Wi, bi);
    attn_kernel<<<BATCH * (SEQ / 64), 256>>>();
    out_kernel<<<(ROWS / 128) * (DIM / 128), 256, OUT_SMEM_BYTES>>>(Wo, bo, out);
}